// round 13
// baseline (speedup 1.0000x reference)
#include <cuda_runtime.h>
#include <cuda_bf16.h>
#include <cstdint>
#include <math.h>

// ---------------- problem constants ----------------
#define D_MODELc 1024
#define SEQc     2048
#define BATCHc   2
#define NTOK     (BATCHc*SEQc)     // 4096 tokens
#define D_MLPc   4096
#define LN_EPSc  1e-5f

// ---------------- device scratch (no runtime allocation allowed) ----------------
__device__ float g_proj[(size_t)NTOK * D_MODELc];               // head_out @ wo
__device__ float g_x1  [(size_t)NTOK * D_MODELc];               // x + LN1(proj)
__device__ float g_mlp [(size_t)NTOK * D_MODELc];               // mlp output
__device__ __nv_bfloat16 g_qkvh[(size_t)NTOK * 3 * D_MODELc];   // qkv split hi
__device__ __nv_bfloat16 g_qkvl[(size_t)NTOK * 3 * D_MODELc];   // qkv split lo
__device__ __nv_bfloat16 g_mlph_hi[(size_t)NTOK * D_MLPc];      // relu(x1@w_in+b_in) split
__device__ __nv_bfloat16 g_mlph_lo[(size_t)NTOK * D_MLPc];
__device__ __nv_bfloat16 g_ahi[(size_t)NTOK * D_MODELc];        // activation split (reused)
__device__ __nv_bfloat16 g_alo[(size_t)NTOK * D_MODELc];
__device__ __nv_bfloat16 g_bhi[(size_t)D_MLPc * D_MODELc];      // weight split (reused)
__device__ __nv_bfloat16 g_blo[(size_t)D_MLPc * D_MODELc];

// ================= PTX helpers (baseline sm_80+ features only) =================
__device__ __forceinline__ uint32_t smem_u32(const void* p) {
    uint32_t a;
    asm("{ .reg .u64 t; cvta.to.shared.u64 t, %1; cvt.u32.u64 %0, t; }" : "=r"(a) : "l"(p));
    return a;
}
#define CP_ASYNC16(dst, src) \
    asm volatile("cp.async.cg.shared.global [%0], [%1], 16;" :: "r"(dst), "l"(src))
#define CP_COMMIT()  asm volatile("cp.async.commit_group;" ::: "memory")
#define CP_WAIT0()   asm volatile("cp.async.wait_group 0;" ::: "memory")
#define CP_WAIT1()   asm volatile("cp.async.wait_group 1;" ::: "memory")
#define LDSM_X4(r0, r1, r2, r3, addr) \
    asm volatile("ldmatrix.sync.aligned.m8n8.x4.shared.b16 {%0,%1,%2,%3}, [%4];" \
        : "=r"(r0), "=r"(r1), "=r"(r2), "=r"(r3) : "r"(addr))
#define MMA_BF16(d, a, b) \
    asm volatile("mma.sync.aligned.m16n8k16.row.col.f32.bf16.bf16.f32 " \
        "{%0,%1,%2,%3},{%4,%5,%6,%7},{%8,%9},{%0,%1,%2,%3};" \
        : "+f"((d)[0]), "+f"((d)[1]), "+f"((d)[2]), "+f"((d)[3]) \
        : "r"((a)[0]), "r"((a)[1]), "r"((a)[2]), "r"((a)[3]), "r"((b)[0]), "r"((b)[1]))
#define PRMT(d, a, b, sel) \
    asm("prmt.b32 %0, %1, %2, %3;" : "=r"(d) : "r"(a), "r"(b), "r"(sel))

// split two fp32 into packed bf16 hi pair + lo (residual) pair
__device__ __forceinline__ void split2(float a, float b, uint32_t& hi, uint32_t& lo) {
    __nv_bfloat16 ha = __float2bfloat16(a), hb = __float2bfloat16(b);
    __nv_bfloat16 la = __float2bfloat16(a - __bfloat162float(ha));
    __nv_bfloat16 lb = __float2bfloat16(b - __bfloat162float(hb));
    __nv_bfloat162 H(ha, hb), L(la, lb);
    hi = *(uint32_t*)&H; lo = *(uint32_t*)&L;
}

// ================= split / transpose kernels =================
__global__ void asplit_kernel(const float* __restrict__ src,
                              __nv_bfloat16* __restrict__ dhi,
                              __nv_bfloat16* __restrict__ dlo, int n4) {
    int i = blockIdx.x * blockDim.x + threadIdx.x;
    if (i >= n4) return;
    float4 v = ((const float4*)src)[i];
    uint32_t h0, l0, h1, l1;
    split2(v.x, v.y, h0, l0);
    split2(v.z, v.w, h1, l1);
    ((uint2*)dhi)[i] = make_uint2(h0, h1);
    ((uint2*)dlo)[i] = make_uint2(l0, l1);
}

// tiled transpose+split: src [R][C] fp32 -> dst [C][R] bf16 hi/lo (vectorized stores)
__global__ void tsplit_kernel(const float* __restrict__ src,
                              __nv_bfloat16* __restrict__ dhi,
                              __nv_bfloat16* __restrict__ dlo, int R, int C) {
    __shared__ float t[32][33];
    int c0 = blockIdx.x * 32, r0 = blockIdx.y * 32;
    int tx = threadIdx.x, ty = threadIdx.y;   // (32, 8)
#pragma unroll
    for (int i = 0; i < 4; i++)
        t[ty + i*8][tx] = src[(size_t)(r0 + ty + i*8) * C + c0 + tx];
    __syncthreads();
    int tid = ty * 32 + tx;
    int sy = tid >> 3;        // 0..31 -> c
    int sx = tid & 7;         // 0..7  -> r group of 4
    float v0 = t[sx*4+0][sy], v1 = t[sx*4+1][sy];
    float v2 = t[sx*4+2][sy], v3 = t[sx*4+3][sy];
    uint32_t h0, l0, h1, l1;
    split2(v0, v1, h0, l0);
    split2(v2, v3, h1, l1);
    size_t o = (size_t)(c0 + sy) * R + r0 + sx * 4;
    *(uint2*)(dhi + o) = make_uint2(h0, h1);
    *(uint2*)(dlo + o) = make_uint2(l0, l1);
}

// wq/wk/wv [16][1024][64] -> Wt [3072][1024] bf16 hi/lo
__global__ void qkv_tsplit_kernel(const float* __restrict__ wq, const float* __restrict__ wk,
                                  const float* __restrict__ wv,
                                  __nv_bfloat16* __restrict__ dhi,
                                  __nv_bfloat16* __restrict__ dlo) {
    __shared__ float t[32][33];
    int z = blockIdx.z, p = z >> 4, h = z & 15;
    const float* src = (p == 0 ? wq : (p == 1 ? wk : wv)) + (size_t)h * 1024 * 64;
    int c0 = blockIdx.x * 32, r0 = blockIdx.y * 32;
    int tx = threadIdx.x, ty = threadIdx.y;
#pragma unroll
    for (int i = 0; i < 4; i++)
        t[ty + i*8][tx] = src[(size_t)(r0 + ty + i*8) * 64 + c0 + tx];
    __syncthreads();
    int nbase = (p << 10) + (h << 6);
    int tid = ty * 32 + tx;
    int sy = tid >> 3;
    int sx = tid & 7;
    float v0 = t[sx*4+0][sy], v1 = t[sx*4+1][sy];
    float v2 = t[sx*4+2][sy], v3 = t[sx*4+3][sy];
    uint32_t h0, l0, h1, l1;
    split2(v0, v1, h0, l0);
    split2(v2, v3, h1, l1);
    size_t o = (size_t)(nbase + c0 + sy) * 1024 + r0 + sx * 4;
    *(uint2*)(dhi + o) = make_uint2(h0, h1);
    *(uint2*)(dlo + o) = make_uint2(l0, l1);
}

// ================= HMMA split-bf16 GEMM (mma.sync m16n8k16) =================
// 128x128 CTA tile, 4 warps (64x64 each), BK=32, 3-stage cp.async, 2 CTAs/SM.
// Row stride 64B (16B-aligned cp.async) + XOR-slot swizzle (chunk c16 stored at
// slot c16 ^ (row & 3)): stage 32768B, 3 stages = 96KB/CTA, 2 CTAs = 192KB.
// wait_group(1): each chunk's loads get ~2 chunk-times of latency cover.
// Term-major MMA issue; per-accumulator order unchanged -> bit-identical numerics.
#define TG_MAT   8192       // 128 rows * 64B
#define TG_STAGE 32768
#define TG_SMEM  98304      // 3 stages

__device__ __forceinline__ uint32_t tg_sw(uint32_t row, uint32_t c16) {
    return (row << 6) + (((c16 ^ row) & 3u) << 4) + ((c16 & ~3u) << 4);
}

__device__ __forceinline__ void tg_load(
        const __nv_bfloat16* __restrict__ Ah, const __nv_bfloat16* __restrict__ Al,
        const __nv_bfloat16* __restrict__ Bh, const __nv_bfloat16* __restrict__ Bl,
        int K, int k0, uint32_t sbase, int tid) {
#pragma unroll
    for (int j = 0; j < 4; j++) {
        int idx = tid + (j << 7);      // 128 threads, 512 chunks per matrix
        uint32_t row = (uint32_t)(idx >> 2), c16 = (uint32_t)(idx & 3);
        uint32_t d = sbase + tg_sw(row, c16);
        const size_t go = (size_t)row * K + k0 + (c16 << 3);
        CP_ASYNC16(d,              Ah + go);
        CP_ASYNC16(d +     TG_MAT, Al + go);
        CP_ASYNC16(d + 2 * TG_MAT, Bh + go);
        CP_ASYNC16(d + 3 * TG_MAT, Bl + go);
    }
}

template<bool RELU, bool SPLITO>
__global__ __launch_bounds__(128, 2)
void tc_gemm_kernel(const __nv_bfloat16* __restrict__ Ahi, const __nv_bfloat16* __restrict__ Alo,
                    const __nv_bfloat16* __restrict__ Bhi, const __nv_bfloat16* __restrict__ Blo,
                    const float* __restrict__ bias, float* __restrict__ C,
                    __nv_bfloat16* __restrict__ Chi, __nv_bfloat16* __restrict__ Clo,
                    int M, int N, int K) {
    extern __shared__ char smem[];
    const uint32_t sb = smem_u32(smem);
    const int tid = threadIdx.x, wid = tid >> 5, lane = tid & 31;
    const int wm = wid >> 1, wn = wid & 1;           // warp grid 2(m) x 2(n), 64x64 each
    const int m0 = blockIdx.y * 128, n0 = blockIdx.x * 128;

    const __nv_bfloat16* pAh = Ahi + (size_t)m0 * K;
    const __nv_bfloat16* pAl = Alo + (size_t)m0 * K;
    const __nv_bfloat16* pBh = Bhi + (size_t)n0 * K;
    const __nv_bfloat16* pBl = Blo + (size_t)n0 * K;

    float acc[4][8][4];
#pragma unroll
    for (int i = 0; i < 4; i++)
#pragma unroll
        for (int j = 0; j < 8; j++)
#pragma unroll
            for (int r = 0; r < 4; r++) acc[i][j][r] = 0.f;

    const int nchunk = K >> 5;
    tg_load(pAh, pAl, pBh, pBl, K, 0, sb, tid);
    CP_COMMIT();
    if (nchunk > 1) {
        tg_load(pAh, pAl, pBh, pBl, K, 32, sb + TG_STAGE, tid);
        CP_COMMIT();
    }

    const uint32_t a_row  = (uint32_t)(wm * 64 + (lane & 15));
    const uint32_t a_c16  = (uint32_t)(lane >> 4);          // + ks*2
    const uint32_t b_rowl = (uint32_t)(((lane >> 4) << 3) + (lane & 7));
    const uint32_t b_c16  = (uint32_t)((lane >> 3) & 1);    // + ks*2

    for (int c = 0; c < nchunk; c++) {
        if (c + 1 < nchunk) { CP_WAIT1(); } else { CP_WAIT0(); }
        __syncthreads();
        if (c + 2 < nchunk) {
            tg_load(pAh, pAl, pBh, pBl, K, (c + 2) << 5,
                    sb + (uint32_t)((c + 2) % 3) * TG_STAGE, tid);
            CP_COMMIT();
        }

        const uint32_t st = sb + (uint32_t)(c % 3) * TG_STAGE;
#pragma unroll
        for (int ks = 0; ks < 2; ks++) {
            uint32_t ah[4][4], al[4][4], bh[8][2], bl[8][2];
            const uint32_t ca = (uint32_t)(ks * 2) + a_c16;
            const uint32_t cb = (uint32_t)(ks * 2) + b_c16;
#pragma unroll
            for (int mt = 0; mt < 4; mt++) {
                uint32_t ad = st + tg_sw(a_row + (uint32_t)(mt * 16), ca);
                LDSM_X4(ah[mt][0], ah[mt][1], ah[mt][2], ah[mt][3], ad);
                LDSM_X4(al[mt][0], al[mt][1], al[mt][2], al[mt][3], ad + TG_MAT);
            }
#pragma unroll
            for (int p = 0; p < 4; p++) {
                uint32_t bd = st + 2 * TG_MAT +
                              tg_sw((uint32_t)(wn * 64 + p * 16) + b_rowl, cb);
                LDSM_X4(bh[2*p][0], bh[2*p][1], bh[2*p+1][0], bh[2*p+1][1], bd);
                LDSM_X4(bl[2*p][0], bl[2*p][1], bl[2*p+1][0], bl[2*p+1][1], bd + TG_MAT);
            }
            // term-major: 32 independent MMAs between accumulator reuses
#pragma unroll
            for (int mt = 0; mt < 4; mt++)
#pragma unroll
                for (int nt = 0; nt < 8; nt++) MMA_BF16(acc[mt][nt], ah[mt], bh[nt]);
#pragma unroll
            for (int mt = 0; mt < 4; mt++)
#pragma unroll
                for (int nt = 0; nt < 8; nt++) MMA_BF16(acc[mt][nt], ah[mt], bl[nt]);
#pragma unroll
            for (int mt = 0; mt < 4; mt++)
#pragma unroll
                for (int nt = 0; nt < 8; nt++) MMA_BF16(acc[mt][nt], al[mt], bh[nt]);
        }
    }

#pragma unroll
    for (int mt = 0; mt < 4; mt++) {
        const int r0 = m0 + wm * 64 + mt * 16 + (lane >> 2);
#pragma unroll
        for (int nt = 0; nt < 8; nt++) {
            const int c0 = n0 + wn * 64 + nt * 8 + ((lane & 3) << 1);
            float bx = bias ? bias[c0]     : 0.f;
            float by = bias ? bias[c0 + 1] : 0.f;
            float v0 = acc[mt][nt][0] + bx, v1 = acc[mt][nt][1] + by;
            float v2 = acc[mt][nt][2] + bx, v3 = acc[mt][nt][3] + by;
            if (RELU) {
                v0 = fmaxf(v0, 0.f); v1 = fmaxf(v1, 0.f);
                v2 = fmaxf(v2, 0.f); v3 = fmaxf(v3, 0.f);
            }
            if (SPLITO) {
                uint32_t hi, lo;
                split2(v0, v1, hi, lo);
                *(uint32_t*)(Chi + (size_t)r0 * N + c0) = hi;
                *(uint32_t*)(Clo + (size_t)r0 * N + c0) = lo;
                split2(v2, v3, hi, lo);
                *(uint32_t*)(Chi + (size_t)(r0 + 8) * N + c0) = hi;
                *(uint32_t*)(Clo + (size_t)(r0 + 8) * N + c0) = lo;
            } else {
                *(float2*)(C + (size_t)r0 * N + c0)       = make_float2(v0, v1);
                *(float2*)(C + (size_t)(r0 + 8) * N + c0) = make_float2(v2, v3);
            }
        }
    }
}

// ================= tensor-core flash attention (causal, split-bf16) =================
// Br=128 rows per CTA, Bc=64 cols per iter, dh=64. 8 warps x 16 rows.
// Inputs are PRE-SPLIT bf16 hi/lo. Term-major MMA issue. (Unchanged from R11.)
#define AT_STRB 144            // smem row stride bytes (72 bf16)
#define AT_K_HI 0
#define AT_K_LO 9216
#define AT_V_HI 18432
#define AT_V_LO 27648
#define AT_SMEM 36864          // Q staging reuses region: hi@0, lo@18432

struct KVPre { uint4 kh[2], kl[2]; uint2 vh[4], vl[4]; };

__device__ __forceinline__ void at_prefetch(
        const __nv_bfloat16* __restrict__ khg, const __nv_bfloat16* __restrict__ klg,
        const __nv_bfloat16* __restrict__ vhg, const __nv_bfloat16* __restrict__ vlg,
        int kc, int tid, KVPre& p) {
    const int rgv = tid >> 4, cgv = tid & 15;
#pragma unroll
    for (int i = 0; i < 2; i++) {
        int idx = tid + (i << 8);
        int row = idx >> 3, c16 = idx & 7;
        size_t o = (size_t)(kc * 64 + row) * 3072 + (c16 << 3);
        p.kh[i] = *(const uint4*)(khg + o);
        p.kl[i] = *(const uint4*)(klg + o);
    }
#pragma unroll
    for (int i = 0; i < 4; i++) {
        size_t o = (size_t)(kc * 64 + 4 * rgv + i) * 3072 + (cgv << 2);
        p.vh[i] = *(const uint2*)(vhg + o);
        p.vl[i] = *(const uint2*)(vlg + o);
    }
}

__global__ __launch_bounds__(256)
void attn_mma_kernel(const __nv_bfloat16* __restrict__ qkvh,
                     const __nv_bfloat16* __restrict__ qkvl,
                     __nv_bfloat16* __restrict__ ohi,
                     __nv_bfloat16* __restrict__ olo) {
    extern __shared__ char smc[];
    const uint32_t sb = smem_u32(smc);
    const int b = blockIdx.y >> 4, h = blockIdx.y & 15;
    const int it = (int)gridDim.x - 1 - (int)blockIdx.x;    // heavy tiles first
    const int r0 = it * 128;
    const int tid = threadIdx.x, w = tid >> 5, lane = tid & 31;

    const size_t base = (size_t)b * SEQc * 3072 + (size_t)(h * 64);
    const __nv_bfloat16* qhg = qkvh + base;
    const __nv_bfloat16* qlg = qkvl + base;
    const __nv_bfloat16* khg = qkvh + base + 1024;
    const __nv_bfloat16* klg = qkvl + base + 1024;
    const __nv_bfloat16* vhg = qkvh + base + 2048;
    const __nv_bfloat16* vlg = qkvl + base + 2048;

    // ---- stage Q (128x64 bf16 hi/lo) into smem: pure copies ----
#pragma unroll
    for (int i = 0; i < 4; i++) {
        int idx = tid + (i << 8);          // 0..1023
        int row = idx >> 3, c16 = idx & 7;
        size_t o = (size_t)(r0 + row) * 3072 + (c16 << 3);
        uint32_t off = (uint32_t)(row * AT_STRB + (c16 << 4));
        *(uint4*)(smc + off)         = *(const uint4*)(qhg + o);
        *(uint4*)(smc + 18432 + off) = *(const uint4*)(qlg + o);
    }
    __syncthreads();

    // Q fragments (register-resident for the whole row tile)
    uint32_t qh[4][4], ql[4][4];
    {
        uint32_t qa = sb + (uint32_t)((w * 16 + (lane & 15)) * AT_STRB) + (uint32_t)(((lane >> 4) << 4));
#pragma unroll
        for (int kt = 0; kt < 4; kt++) {
            LDSM_X4(qh[kt][0], qh[kt][1], qh[kt][2], qh[kt][3], qa + kt * 32);
            LDSM_X4(ql[kt][0], ql[kt][1], ql[kt][2], ql[kt][3], qa + 18432 + kt * 32);
        }
    }

    float acc[8][4];
#pragma unroll
    for (int nt = 0; nt < 8; nt++)
#pragma unroll
        for (int r = 0; r < 4; r++) acc[nt][r] = 0.f;
    float m0 = -1e30f, m1 = -1e30f, l0 = 0.f, l1 = 0.f;

    const int row0 = r0 + w * 16 + (lane >> 2);
    const int row1 = row0 + 8;
    const int ktiles = 2 * it + 2;
    const int diag0 = 2 * it;
    const uint32_t brow = (uint32_t)(((lane >> 4) << 3) + (lane & 7));
    const uint32_t bko  = (uint32_t)(((lane >> 3) & 1) << 4);
    const int rgv = tid >> 4, cgv = tid & 15;

    KVPre pre;
    at_prefetch(khg, klg, vhg, vlg, 0, tid, pre);

    for (int kc = 0; kc < ktiles; kc++) {
        __syncthreads();          // previous tile consumed (or Q frags loaded)

        // ---- store prefetched K (K-major) hi/lo: straight copies ----
#pragma unroll
        for (int i = 0; i < 2; i++) {
            int idx = tid + (i << 8);
            int row = idx >> 3, c16 = idx & 7;
            uint32_t off = (uint32_t)(row * AT_STRB + (c16 << 4));
            *(uint4*)(smc + AT_K_HI + off) = pre.kh[i];
            *(uint4*)(smc + AT_K_LO + off) = pre.kl[i];
        }
        // ---- store prefetched V transposed: PRMT 4x4 bf16 transpose ----
        {
            uint32_t inh[4][2] = {{pre.vh[0].x, pre.vh[0].y}, {pre.vh[1].x, pre.vh[1].y},
                                  {pre.vh[2].x, pre.vh[2].y}, {pre.vh[3].x, pre.vh[3].y}};
            uint32_t inl[4][2] = {{pre.vl[0].x, pre.vl[0].y}, {pre.vl[1].x, pre.vl[1].y},
                                  {pre.vl[2].x, pre.vl[2].y}, {pre.vl[3].x, pre.vl[3].y}};
#pragma unroll
            for (int dd = 0; dd < 4; dd++) {
                int col = (cgv << 2) + dd;
                int q = dd >> 1;
                uint32_t sel = (dd & 1) ? 0x7632u : 0x5410u;
                uint32_t h01, h23, l01, l23;
                PRMT(h01, inh[0][q], inh[1][q], sel);
                PRMT(h23, inh[2][q], inh[3][q], sel);
                PRMT(l01, inl[0][q], inl[1][q], sel);
                PRMT(l23, inl[2][q], inl[3][q], sel);
                uint32_t sw = (uint32_t)(((col >> 3) & 3) << 4);
                uint32_t byte = (uint32_t)(col * AT_STRB) + (((uint32_t)(rgv << 3)) ^ sw);
                *(uint2*)(smc + AT_V_HI + byte) = make_uint2(h01, h23);
                *(uint2*)(smc + AT_V_LO + byte) = make_uint2(l01, l23);
            }
        }
        __syncthreads();

        // prefetch next tile's gmem data (overlaps with MMAs below)
        if (kc + 1 < ktiles) at_prefetch(khg, klg, vhg, vlg, kc + 1, tid, pre);

        // ---- S = Q K^T (split, 3 terms, term-major issue) ----
        float s[8][4];
#pragma unroll
        for (int nt = 0; nt < 8; nt++)
#pragma unroll
            for (int r = 0; r < 4; r++) s[nt][r] = 0.f;
#pragma unroll
        for (int kt = 0; kt < 4; kt++) {
            uint32_t bh[8][2], bl[8][2];
#pragma unroll
            for (int p = 0; p < 4; p++) {
                uint32_t bd = sb + AT_K_HI + (p * 16 + brow) * AT_STRB + kt * 32 + bko;
                LDSM_X4(bh[2*p][0], bh[2*p][1], bh[2*p+1][0], bh[2*p+1][1], bd);
                LDSM_X4(bl[2*p][0], bl[2*p][1], bl[2*p+1][0], bl[2*p+1][1], bd + 9216);
            }
#pragma unroll
            for (int nt = 0; nt < 8; nt++) MMA_BF16(s[nt], qh[kt], bh[nt]);
#pragma unroll
            for (int nt = 0; nt < 8; nt++) MMA_BF16(s[nt], qh[kt], bl[nt]);
#pragma unroll
            for (int nt = 0; nt < 8; nt++) MMA_BF16(s[nt], ql[kt], bh[nt]);
        }
#pragma unroll
        for (int nt = 0; nt < 8; nt++)
#pragma unroll
            for (int r = 0; r < 4; r++) s[nt][r] *= 0.125f;

        // ---- causal mask (diagonal tiles only) ----
        if (kc >= diag0) {
            int colb = kc * 64 + ((lane & 3) << 1);
#pragma unroll
            for (int nt = 0; nt < 8; nt++) {
                int c0 = colb + nt * 8;
                if (c0     > row0) s[nt][0] = -1e30f;
                if (c0 + 1 > row0) s[nt][1] = -1e30f;
                if (c0     > row1) s[nt][2] = -1e30f;
                if (c0 + 1 > row1) s[nt][3] = -1e30f;
            }
        }

        // ---- online softmax (rows r and r+8; 4-lane group reductions) ----
        float mx0 = -1e30f, mx1 = -1e30f;
#pragma unroll
        for (int nt = 0; nt < 8; nt++) {
            mx0 = fmaxf(mx0, fmaxf(s[nt][0], s[nt][1]));
            mx1 = fmaxf(mx1, fmaxf(s[nt][2], s[nt][3]));
        }
        mx0 = fmaxf(mx0, __shfl_xor_sync(0xffffffffu, mx0, 1));
        mx0 = fmaxf(mx0, __shfl_xor_sync(0xffffffffu, mx0, 2));
        mx1 = fmaxf(mx1, __shfl_xor_sync(0xffffffffu, mx1, 1));
        mx1 = fmaxf(mx1, __shfl_xor_sync(0xffffffffu, mx1, 2));
        float nm0 = fmaxf(m0, mx0), nm1 = fmaxf(m1, mx1);
        float sum0 = 0.f, sum1 = 0.f;
#pragma unroll
        for (int nt = 0; nt < 8; nt++) {
            s[nt][0] = __expf(s[nt][0] - nm0); sum0 += s[nt][0];
            s[nt][1] = __expf(s[nt][1] - nm0); sum0 += s[nt][1];
            s[nt][2] = __expf(s[nt][2] - nm1); sum1 += s[nt][2];
            s[nt][3] = __expf(s[nt][3] - nm1); sum1 += s[nt][3];
        }
        sum0 += __shfl_xor_sync(0xffffffffu, sum0, 1);
        sum0 += __shfl_xor_sync(0xffffffffu, sum0, 2);
        sum1 += __shfl_xor_sync(0xffffffffu, sum1, 1);
        sum1 += __shfl_xor_sync(0xffffffffu, sum1, 2);
        float a0 = __expf(m0 - nm0), a1 = __expf(m1 - nm1);
        m0 = nm0; m1 = nm1;
        l0 = l0 * a0 + sum0; l1 = l1 * a1 + sum1;
#pragma unroll
        for (int nt = 0; nt < 8; nt++) {
            acc[nt][0] *= a0; acc[nt][1] *= a0;
            acc[nt][2] *= a1; acc[nt][3] *= a1;
        }

        // ---- repack S accumulator fragments into P A-fragments (hi/lo) ----
        uint32_t ph[4][4], pl[4][4];
#pragma unroll
        for (int kt = 0; kt < 4; kt++) {
            int e = 2 * kt, o = 2 * kt + 1;
            split2(s[e][0], s[e][1], ph[kt][0], pl[kt][0]);
            split2(s[e][2], s[e][3], ph[kt][1], pl[kt][1]);
            split2(s[o][0], s[o][1], ph[kt][2], pl[kt][2]);
            split2(s[o][2], s[o][3], ph[kt][3], pl[kt][3]);
        }

        // ---- O += P @ V (split, 3 terms, term-major issue; swizzled V reads) ----
#pragma unroll
        for (int kt = 0; kt < 4; kt++) {
            uint32_t vh[8][2], vl[8][2];
#pragma unroll
            for (int p = 0; p < 4; p++) {
                uint32_t dlane = (uint32_t)(p * 16) + brow;
                uint32_t sw = ((dlane >> 3) & 3) << 4;
                uint32_t bd = sb + AT_V_HI + dlane * AT_STRB + ((uint32_t)(kt * 32 + bko) ^ sw);
                LDSM_X4(vh[2*p][0], vh[2*p][1], vh[2*p+1][0], vh[2*p+1][1], bd);
                LDSM_X4(vl[2*p][0], vl[2*p][1], vl[2*p+1][0], vl[2*p+1][1], bd + 9216);
            }
#pragma unroll
            for (int nt = 0; nt < 8; nt++) MMA_BF16(acc[nt], ph[kt], vh[nt]);
#pragma unroll
            for (int nt = 0; nt < 8; nt++) MMA_BF16(acc[nt], ph[kt], vl[nt]);
#pragma unroll
            for (int nt = 0; nt < 8; nt++) MMA_BF16(acc[nt], pl[kt], vh[nt]);
        }
    }

    // ---- epilogue: normalize and write bf16 hi/lo (concat head layout) ----
    float inv0 = 1.f / l0, inv1 = 1.f / l1;
    const int tok0 = b * SEQc + row0;
#pragma unroll
    for (int nt = 0; nt < 8; nt++) {
        int col = h * 64 + nt * 8 + ((lane & 3) << 1);
        uint32_t hi, lo;
        split2(acc[nt][0] * inv0, acc[nt][1] * inv0, hi, lo);
        *(uint32_t*)(ohi + (size_t)tok0 * 1024 + col) = hi;
        *(uint32_t*)(olo + (size_t)tok0 * 1024 + col) = lo;
        split2(acc[nt][2] * inv1, acc[nt][3] * inv1, hi, lo);
        *(uint32_t*)(ohi + (size_t)(tok0 + 8) * 1024 + col) = hi;
        *(uint32_t*)(olo + (size_t)(tok0 + 8) * 1024 + col) = lo;
    }
}

// ---------------- LayerNorm + residual ----------------
template<bool SPLITO>
__global__ void ln_residual_kernel(const float* __restrict__ resid,
                                   const float* __restrict__ v,
                                   const float* __restrict__ g,
                                   const float* __restrict__ beta,
                                   float* __restrict__ out,
                                   __nv_bfloat16* __restrict__ ohi,
                                   __nv_bfloat16* __restrict__ olo) {
    __shared__ float red[16];
    const int row = blockIdx.x;
    const int t = threadIdx.x;
    const float* vr = v + (size_t)row * D_MODELc;
    float4 xv = *(const float4*)(vr + t * 4);
    float s  = xv.x + xv.y + xv.z + xv.w;
    float s2 = xv.x * xv.x + xv.y * xv.y + xv.z * xv.z + xv.w * xv.w;
#pragma unroll
    for (int o = 16; o; o >>= 1) {
        s  += __shfl_xor_sync(0xffffffffu, s,  o);
        s2 += __shfl_xor_sync(0xffffffffu, s2, o);
    }
    int wid = t >> 5;
    if ((t & 31) == 0) { red[wid] = s; red[8 + wid] = s2; }
    __syncthreads();
    float S = 0.f, S2 = 0.f;
#pragma unroll
    for (int i = 0; i < 8; i++) { S += red[i]; S2 += red[8 + i]; }
    float mu   = S * (1.f / D_MODELc);
    float var  = S2 * (1.f / D_MODELc) - mu * mu;
    float rstd = rsqrtf(var + LN_EPSc);

    int c = t * 4;
    float4 rr = *(const float4*)(resid + (size_t)row * D_MODELc + c);
    float4 gg = *(const float4*)(g + c);
    float4 bb = *(const float4*)(beta + c);
    float4 o;
    o.x = rr.x + (xv.x - mu) * rstd * gg.x + bb.x;
    o.y = rr.y + (xv.y - mu) * rstd * gg.y + bb.y;
    o.z = rr.z + (xv.z - mu) * rstd * gg.z + bb.z;
    o.w = rr.w + (xv.w - mu) * rstd * gg.w + bb.w;
    *(float4*)(out + (size_t)row * D_MODELc + c) = o;
    if (SPLITO) {
        uint32_t h0, l0, h1, l1;
        split2(o.x, o.y, h0, l0);
        split2(o.z, o.w, h1, l1);
        *(uint2*)(ohi + (size_t)row * D_MODELc + c) = make_uint2(h0, h1);
        *(uint2*)(olo + (size_t)row * D_MODELc + c) = make_uint2(l0, l1);
    }
}

// ---------------- launch ----------------
extern "C" void kernel_launch(void* const* d_in, const int* in_sizes, int n_in,
                              void* d_out, int out_size) {
    (void)in_sizes; (void)n_in; (void)out_size;
    const float* x     = (const float*)d_in[0];
    const float* wq    = (const float*)d_in[1];
    const float* wk    = (const float*)d_in[2];
    const float* wv    = (const float*)d_in[3];
    const float* wo    = (const float*)d_in[4];
    const float* w_in  = (const float*)d_in[5];
    const float* b_in  = (const float*)d_in[6];
    const float* w_out = (const float*)d_in[7];
    const float* b_out = (const float*)d_in[8];
    const float* g1    = (const float*)d_in[9];
    const float* bt1   = (const float*)d_in[10];
    const float* g2    = (const float*)d_in[11];
    const float* bt2   = (const float*)d_in[12];
    float* out = (float*)d_out;

    float *proj, *x1, *mlp;
    __nv_bfloat16 *qkvh, *qkvl, *ahi, *alo, *bhi, *blo, *mh, *ml;
    cudaGetSymbolAddress((void**)&proj, g_proj);
    cudaGetSymbolAddress((void**)&x1,   g_x1);
    cudaGetSymbolAddress((void**)&mlp,  g_mlp);
    cudaGetSymbolAddress((void**)&qkvh, g_qkvh);
    cudaGetSymbolAddress((void**)&qkvl, g_qkvl);
    cudaGetSymbolAddress((void**)&ahi,  g_ahi);
    cudaGetSymbolAddress((void**)&alo,  g_alo);
    cudaGetSymbolAddress((void**)&bhi,  g_bhi);
    cudaGetSymbolAddress((void**)&blo,  g_blo);
    cudaGetSymbolAddress((void**)&mh,   g_mlph_hi);
    cudaGetSymbolAddress((void**)&ml,   g_mlph_lo);

    cudaFuncSetAttribute(tc_gemm_kernel<false, false>, cudaFuncAttributeMaxDynamicSharedMemorySize, TG_SMEM);
    cudaFuncSetAttribute(tc_gemm_kernel<false, true>,  cudaFuncAttributeMaxDynamicSharedMemorySize, TG_SMEM);
    cudaFuncSetAttribute(tc_gemm_kernel<true,  true>,  cudaFuncAttributeMaxDynamicSharedMemorySize, TG_SMEM);
    cudaFuncSetAttribute(attn_mma_kernel, cudaFuncAttributeMaxDynamicSharedMemorySize, AT_SMEM);

    dim3 tsb(32, 8);

    // ---- QKV projection: [4096,1024] @ [1024,3072], split bf16 output ----
    qkv_tsplit_kernel<<<dim3(2, 32, 48), tsb>>>(wq, wk, wv, bhi, blo);
    asplit_kernel<<<(NTOK * D_MODELc / 4 + 255) / 256, 256>>>(x, ahi, alo, NTOK * D_MODELc / 4);
    tc_gemm_kernel<false, true><<<dim3(24, 32), 128, TG_SMEM>>>(
        ahi, alo, bhi, blo, nullptr, nullptr, qkvh, qkvl, NTOK, 3072, 1024);

    // ---- tensor-core causal flash attention -> bf16 hi/lo (overwrites ahi/alo) ----
    attn_mma_kernel<<<dim3(SEQc / 128, BATCHc * 16), 256, AT_SMEM>>>(qkvh, qkvl, ahi, alo);

    // ---- output projection: att @ wo ----
    tsplit_kernel<<<dim3(32, 32), tsb>>>(wo, bhi, blo, 1024, 1024);
    tc_gemm_kernel<false, false><<<dim3(8, 32), 128, TG_SMEM>>>(
        ahi, alo, bhi, blo, nullptr, proj, nullptr, nullptr, NTOK, 1024, 1024);

    // ---- x1 = x + LN(proj), fused split into ahi/alo ----
    ln_residual_kernel<true><<<NTOK, 256>>>(x, proj, g1, bt1, x1, ahi, alo);

    // ---- MLP in: relu(x1 @ w_in + b_in), fused split output ----
    tsplit_kernel<<<dim3(128, 32), tsb>>>(w_in, bhi, blo, 1024, 4096);
    tc_gemm_kernel<true, true><<<dim3(32, 32), 128, TG_SMEM>>>(
        ahi, alo, bhi, blo, b_in, nullptr, mh, ml, NTOK, 4096, 1024);

    // ---- MLP out: mlph @ w_out + b_out ----
    tsplit_kernel<<<dim3(32, 128), tsb>>>(w_out, bhi, blo, 4096, 1024);
    tc_gemm_kernel<false, false><<<dim3(8, 32), 128, TG_SMEM>>>(
        mh, ml, bhi, blo, b_out, mlp, nullptr, nullptr, NTOK, 1024, 4096);

    // ---- out = x1 + LN(mlp) ----
    ln_residual_kernel<false><<<NTOK, 256>>>(x1, mlp, g2, bt2, out, nullptr, nullptr);
}

// round 14
// speedup vs baseline: 1.4016x; 1.4016x over previous
#include <cuda_runtime.h>
#include <cuda_bf16.h>
#include <cstdint>
#include <math.h>

// ---------------- problem constants ----------------
#define D_MODELc 1024
#define SEQc     2048
#define BATCHc   2
#define NTOK     (BATCHc*SEQc)     // 4096 tokens
#define D_MLPc   4096
#define LN_EPSc  1e-5f

// ---------------- device scratch (no runtime allocation allowed) ----------------
__device__ float g_proj[(size_t)NTOK * D_MODELc];               // head_out @ wo
__device__ float g_x1  [(size_t)NTOK * D_MODELc];               // x + LN1(proj)
__device__ float g_mlp [(size_t)NTOK * D_MODELc];               // mlp output
__device__ __nv_bfloat16 g_qkvh[(size_t)NTOK * 3 * D_MODELc];   // qkv split hi
__device__ __nv_bfloat16 g_qkvl[(size_t)NTOK * 3 * D_MODELc];   // qkv split lo
__device__ __nv_bfloat16 g_mlph_hi[(size_t)NTOK * D_MLPc];      // relu(x1@w_in+b_in) split
__device__ __nv_bfloat16 g_mlph_lo[(size_t)NTOK * D_MLPc];
__device__ __nv_bfloat16 g_ahi[(size_t)NTOK * D_MODELc];        // activation split (reused)
__device__ __nv_bfloat16 g_alo[(size_t)NTOK * D_MODELc];
// dedicated weight buffers (enable aux-stream overlap with no reuse hazards)
__device__ __nv_bfloat16 g_wqh[(size_t)3072 * 1024], g_wql[(size_t)3072 * 1024];
__device__ __nv_bfloat16 g_woh[(size_t)1024 * 1024], g_wol[(size_t)1024 * 1024];
__device__ __nv_bfloat16 g_wih[(size_t)4096 * 1024], g_wil[(size_t)4096 * 1024];
__device__ __nv_bfloat16 g_wgh[(size_t)1024 * 4096], g_wgl[(size_t)1024 * 4096];

// ================= PTX helpers (baseline sm_80+ features only) =================
__device__ __forceinline__ uint32_t smem_u32(const void* p) {
    uint32_t a;
    asm("{ .reg .u64 t; cvta.to.shared.u64 t, %1; cvt.u32.u64 %0, t; }" : "=r"(a) : "l"(p));
    return a;
}
#define CP_ASYNC16(dst, src) \
    asm volatile("cp.async.cg.shared.global [%0], [%1], 16;" :: "r"(dst), "l"(src))
#define CP_COMMIT()  asm volatile("cp.async.commit_group;" ::: "memory")
#define CP_WAIT0()   asm volatile("cp.async.wait_group 0;" ::: "memory")
#define LDSM_X4(r0, r1, r2, r3, addr) \
    asm volatile("ldmatrix.sync.aligned.m8n8.x4.shared.b16 {%0,%1,%2,%3}, [%4];" \
        : "=r"(r0), "=r"(r1), "=r"(r2), "=r"(r3) : "r"(addr))
#define MMA_BF16(d, a, b) \
    asm volatile("mma.sync.aligned.m16n8k16.row.col.f32.bf16.bf16.f32 " \
        "{%0,%1,%2,%3},{%4,%5,%6,%7},{%8,%9},{%0,%1,%2,%3};" \
        : "+f"((d)[0]), "+f"((d)[1]), "+f"((d)[2]), "+f"((d)[3]) \
        : "r"((a)[0]), "r"((a)[1]), "r"((a)[2]), "r"((a)[3]), "r"((b)[0]), "r"((b)[1]))
#define PRMT(d, a, b, sel) \
    asm("prmt.b32 %0, %1, %2, %3;" : "=r"(d) : "r"(a), "r"(b), "r"(sel))

// split two fp32 into packed bf16 hi pair + lo (residual) pair
__device__ __forceinline__ void split2(float a, float b, uint32_t& hi, uint32_t& lo) {
    __nv_bfloat16 ha = __float2bfloat16(a), hb = __float2bfloat16(b);
    __nv_bfloat16 la = __float2bfloat16(a - __bfloat162float(ha));
    __nv_bfloat16 lb = __float2bfloat16(b - __bfloat162float(hb));
    __nv_bfloat162 H(ha, hb), L(la, lb);
    hi = *(uint32_t*)&H; lo = *(uint32_t*)&L;
}

// ================= split / transpose kernels =================
__global__ void asplit_kernel(const float* __restrict__ src,
                              __nv_bfloat16* __restrict__ dhi,
                              __nv_bfloat16* __restrict__ dlo, int n4) {
    int i = blockIdx.x * blockDim.x + threadIdx.x;
    if (i >= n4) return;
    float4 v = ((const float4*)src)[i];
    uint32_t h0, l0, h1, l1;
    split2(v.x, v.y, h0, l0);
    split2(v.z, v.w, h1, l1);
    ((uint2*)dhi)[i] = make_uint2(h0, h1);
    ((uint2*)dlo)[i] = make_uint2(l0, l1);
}

// tiled transpose+split: src [R][C] fp32 -> dst [C][R] bf16 hi/lo (vectorized stores)
__global__ void tsplit_kernel(const float* __restrict__ src,
                              __nv_bfloat16* __restrict__ dhi,
                              __nv_bfloat16* __restrict__ dlo, int R, int C) {
    __shared__ float t[32][33];
    int c0 = blockIdx.x * 32, r0 = blockIdx.y * 32;
    int tx = threadIdx.x, ty = threadIdx.y;   // (32, 8)
#pragma unroll
    for (int i = 0; i < 4; i++)
        t[ty + i*8][tx] = src[(size_t)(r0 + ty + i*8) * C + c0 + tx];
    __syncthreads();
    int tid = ty * 32 + tx;
    int sy = tid >> 3;        // 0..31 -> c
    int sx = tid & 7;         // 0..7  -> r group of 4
    float v0 = t[sx*4+0][sy], v1 = t[sx*4+1][sy];
    float v2 = t[sx*4+2][sy], v3 = t[sx*4+3][sy];
    uint32_t h0, l0, h1, l1;
    split2(v0, v1, h0, l0);
    split2(v2, v3, h1, l1);
    size_t o = (size_t)(c0 + sy) * R + r0 + sx * 4;
    *(uint2*)(dhi + o) = make_uint2(h0, h1);
    *(uint2*)(dlo + o) = make_uint2(l0, l1);
}

// wq/wk/wv [16][1024][64] -> Wt [3072][1024] bf16 hi/lo
__global__ void qkv_tsplit_kernel(const float* __restrict__ wq, const float* __restrict__ wk,
                                  const float* __restrict__ wv,
                                  __nv_bfloat16* __restrict__ dhi,
                                  __nv_bfloat16* __restrict__ dlo) {
    __shared__ float t[32][33];
    int z = blockIdx.z, p = z >> 4, h = z & 15;
    const float* src = (p == 0 ? wq : (p == 1 ? wk : wv)) + (size_t)h * 1024 * 64;
    int c0 = blockIdx.x * 32, r0 = blockIdx.y * 32;
    int tx = threadIdx.x, ty = threadIdx.y;
#pragma unroll
    for (int i = 0; i < 4; i++)
        t[ty + i*8][tx] = src[(size_t)(r0 + ty + i*8) * 64 + c0 + tx];
    __syncthreads();
    int nbase = (p << 10) + (h << 6);
    int tid = ty * 32 + tx;
    int sy = tid >> 3;
    int sx = tid & 7;
    float v0 = t[sx*4+0][sy], v1 = t[sx*4+1][sy];
    float v2 = t[sx*4+2][sy], v3 = t[sx*4+3][sy];
    uint32_t h0, l0, h1, l1;
    split2(v0, v1, h0, l0);
    split2(v2, v3, h1, l1);
    size_t o = (size_t)(nbase + c0 + sy) * 1024 + r0 + sx * 4;
    *(uint2*)(dhi + o) = make_uint2(h0, h1);
    *(uint2*)(dlo + o) = make_uint2(l0, l1);
}

// ================= HMMA split-bf16 GEMM (mma.sync m16n8k16) =================
// EXACT R11 config (proven 1163us): 128x128 CTA tile, 4 warps (64x64), BK=32,
// stride 80B, 2-stage cp.async, 2 CTAs/SM, term-major MMA issue.
#define TG_STRB  80
#define TG_MAT   10240      // 128*80
#define TG_STAGE 40960
#define TG_SMEM  81920      // 2 stages

__device__ __forceinline__ void tg_load(
        const __nv_bfloat16* __restrict__ Ah, const __nv_bfloat16* __restrict__ Al,
        const __nv_bfloat16* __restrict__ Bh, const __nv_bfloat16* __restrict__ Bl,
        int K, int k0, uint32_t sbase, int tid) {
#pragma unroll
    for (int j = 0; j < 4; j++) {
        int idx = tid + (j << 7);      // 128 threads, 512 chunks per matrix
        int row = idx >> 2, kc = idx & 3;
        uint32_t d = sbase + row * TG_STRB + (kc << 4);
        const size_t go = (size_t)row * K + k0 + (kc << 3);
        CP_ASYNC16(d,              Ah + go);
        CP_ASYNC16(d +     TG_MAT, Al + go);
        CP_ASYNC16(d + 2 * TG_MAT, Bh + go);
        CP_ASYNC16(d + 3 * TG_MAT, Bl + go);
    }
}

template<bool RELU, bool SPLITO>
__global__ __launch_bounds__(128, 2)
void tc_gemm_kernel(const __nv_bfloat16* __restrict__ Ahi, const __nv_bfloat16* __restrict__ Alo,
                    const __nv_bfloat16* __restrict__ Bhi, const __nv_bfloat16* __restrict__ Blo,
                    const float* __restrict__ bias, float* __restrict__ C,
                    __nv_bfloat16* __restrict__ Chi, __nv_bfloat16* __restrict__ Clo,
                    int M, int N, int K) {
    extern __shared__ char smem[];
    const uint32_t sb = smem_u32(smem);
    const int tid = threadIdx.x, wid = tid >> 5, lane = tid & 31;
    const int wm = wid >> 1, wn = wid & 1;           // warp grid 2(m) x 2(n), 64x64 each
    const int m0 = blockIdx.y * 128, n0 = blockIdx.x * 128;

    const __nv_bfloat16* pAh = Ahi + (size_t)m0 * K;
    const __nv_bfloat16* pAl = Alo + (size_t)m0 * K;
    const __nv_bfloat16* pBh = Bhi + (size_t)n0 * K;
    const __nv_bfloat16* pBl = Blo + (size_t)n0 * K;

    float acc[4][8][4];
#pragma unroll
    for (int i = 0; i < 4; i++)
#pragma unroll
        for (int j = 0; j < 8; j++)
#pragma unroll
            for (int r = 0; r < 4; r++) acc[i][j][r] = 0.f;

    const int nchunk = K >> 5;
    tg_load(pAh, pAl, pBh, pBl, K, 0, sb, tid);
    CP_COMMIT();

    const uint32_t a_row  = (uint32_t)(wm * 64 + (lane & 15));
    const uint32_t a_koff = (uint32_t)((lane >> 4) << 4);
    const uint32_t b_rowl = (uint32_t)(((lane >> 4) << 3) + (lane & 7));
    const uint32_t b_koff = (uint32_t)(((lane >> 3) & 1) << 4);

    for (int c = 0; c < nchunk; c++) {
        CP_WAIT0();
        __syncthreads();
        if (c + 1 < nchunk) {
            tg_load(pAh, pAl, pBh, pBl, K, (c + 1) << 5,
                    sb + (uint32_t)((c + 1) & 1) * TG_STAGE, tid);
            CP_COMMIT();
        }

        const uint32_t st = sb + (uint32_t)(c & 1) * TG_STAGE;
#pragma unroll
        for (int ks = 0; ks < 2; ks++) {
            uint32_t ah[4][4], al[4][4], bh[8][2], bl[8][2];
#pragma unroll
            for (int mt = 0; mt < 4; mt++) {
                uint32_t ad = st + (a_row + mt * 16) * TG_STRB + ks * 32 + a_koff;
                LDSM_X4(ah[mt][0], ah[mt][1], ah[mt][2], ah[mt][3], ad);
                LDSM_X4(al[mt][0], al[mt][1], al[mt][2], al[mt][3], ad + TG_MAT);
            }
#pragma unroll
            for (int p = 0; p < 4; p++) {
                uint32_t bd = st + 2 * TG_MAT +
                              (wn * 64 + p * 16 + b_rowl) * TG_STRB + ks * 32 + b_koff;
                LDSM_X4(bh[2*p][0], bh[2*p][1], bh[2*p+1][0], bh[2*p+1][1], bd);
                LDSM_X4(bl[2*p][0], bl[2*p][1], bl[2*p+1][0], bl[2*p+1][1], bd + TG_MAT);
            }
            // term-major: 32 independent MMAs between accumulator reuses
#pragma unroll
            for (int mt = 0; mt < 4; mt++)
#pragma unroll
                for (int nt = 0; nt < 8; nt++) MMA_BF16(acc[mt][nt], ah[mt], bh[nt]);
#pragma unroll
            for (int mt = 0; mt < 4; mt++)
#pragma unroll
                for (int nt = 0; nt < 8; nt++) MMA_BF16(acc[mt][nt], ah[mt], bl[nt]);
#pragma unroll
            for (int mt = 0; mt < 4; mt++)
#pragma unroll
                for (int nt = 0; nt < 8; nt++) MMA_BF16(acc[mt][nt], al[mt], bh[nt]);
        }
    }

#pragma unroll
    for (int mt = 0; mt < 4; mt++) {
        const int r0 = m0 + wm * 64 + mt * 16 + (lane >> 2);
#pragma unroll
        for (int nt = 0; nt < 8; nt++) {
            const int c0 = n0 + wn * 64 + nt * 8 + ((lane & 3) << 1);
            float bx = bias ? bias[c0]     : 0.f;
            float by = bias ? bias[c0 + 1] : 0.f;
            float v0 = acc[mt][nt][0] + bx, v1 = acc[mt][nt][1] + by;
            float v2 = acc[mt][nt][2] + bx, v3 = acc[mt][nt][3] + by;
            if (RELU) {
                v0 = fmaxf(v0, 0.f); v1 = fmaxf(v1, 0.f);
                v2 = fmaxf(v2, 0.f); v3 = fmaxf(v3, 0.f);
            }
            if (SPLITO) {
                uint32_t hi, lo;
                split2(v0, v1, hi, lo);
                *(uint32_t*)(Chi + (size_t)r0 * N + c0) = hi;
                *(uint32_t*)(Clo + (size_t)r0 * N + c0) = lo;
                split2(v2, v3, hi, lo);
                *(uint32_t*)(Chi + (size_t)(r0 + 8) * N + c0) = hi;
                *(uint32_t*)(Clo + (size_t)(r0 + 8) * N + c0) = lo;
            } else {
                *(float2*)(C + (size_t)r0 * N + c0)       = make_float2(v0, v1);
                *(float2*)(C + (size_t)(r0 + 8) * N + c0) = make_float2(v2, v3);
            }
        }
    }
}

// ================= tensor-core flash attention (causal, split-bf16) =================
// R11 kernel + fully-masked-tile skip (bit-identical: skipped tiles contributed
// exact zeros and alpha=1).
#define AT_STRB 144            // smem row stride bytes (72 bf16)
#define AT_K_HI 0
#define AT_K_LO 9216
#define AT_V_HI 18432
#define AT_V_LO 27648
#define AT_SMEM 36864          // Q staging reuses region: hi@0, lo@18432

struct KVPre { uint4 kh[2], kl[2]; uint2 vh[4], vl[4]; };

__device__ __forceinline__ void at_prefetch(
        const __nv_bfloat16* __restrict__ khg, const __nv_bfloat16* __restrict__ klg,
        const __nv_bfloat16* __restrict__ vhg, const __nv_bfloat16* __restrict__ vlg,
        int kc, int tid, KVPre& p) {
    const int rgv = tid >> 4, cgv = tid & 15;
#pragma unroll
    for (int i = 0; i < 2; i++) {
        int idx = tid + (i << 8);
        int row = idx >> 3, c16 = idx & 7;
        size_t o = (size_t)(kc * 64 + row) * 3072 + (c16 << 3);
        p.kh[i] = *(const uint4*)(khg + o);
        p.kl[i] = *(const uint4*)(klg + o);
    }
#pragma unroll
    for (int i = 0; i < 4; i++) {
        size_t o = (size_t)(kc * 64 + 4 * rgv + i) * 3072 + (cgv << 2);
        p.vh[i] = *(const uint2*)(vhg + o);
        p.vl[i] = *(const uint2*)(vlg + o);
    }
}

__global__ __launch_bounds__(256)
void attn_mma_kernel(const __nv_bfloat16* __restrict__ qkvh,
                     const __nv_bfloat16* __restrict__ qkvl,
                     __nv_bfloat16* __restrict__ ohi,
                     __nv_bfloat16* __restrict__ olo) {
    extern __shared__ char smc[];
    const uint32_t sb = smem_u32(smc);
    const int b = blockIdx.y >> 4, h = blockIdx.y & 15;
    const int it = (int)gridDim.x - 1 - (int)blockIdx.x;    // heavy tiles first
    const int r0 = it * 128;
    const int tid = threadIdx.x, w = tid >> 5, lane = tid & 31;

    const size_t base = (size_t)b * SEQc * 3072 + (size_t)(h * 64);
    const __nv_bfloat16* qhg = qkvh + base;
    const __nv_bfloat16* qlg = qkvl + base;
    const __nv_bfloat16* khg = qkvh + base + 1024;
    const __nv_bfloat16* klg = qkvl + base + 1024;
    const __nv_bfloat16* vhg = qkvh + base + 2048;
    const __nv_bfloat16* vlg = qkvl + base + 2048;

    // ---- stage Q (128x64 bf16 hi/lo) into smem: pure copies ----
#pragma unroll
    for (int i = 0; i < 4; i++) {
        int idx = tid + (i << 8);          // 0..1023
        int row = idx >> 3, c16 = idx & 7;
        size_t o = (size_t)(r0 + row) * 3072 + (c16 << 3);
        uint32_t off = (uint32_t)(row * AT_STRB + (c16 << 4));
        *(uint4*)(smc + off)         = *(const uint4*)(qhg + o);
        *(uint4*)(smc + 18432 + off) = *(const uint4*)(qlg + o);
    }
    __syncthreads();

    // Q fragments (register-resident for the whole row tile)
    uint32_t qh[4][4], ql[4][4];
    {
        uint32_t qa = sb + (uint32_t)((w * 16 + (lane & 15)) * AT_STRB) + (uint32_t)(((lane >> 4) << 4));
#pragma unroll
        for (int kt = 0; kt < 4; kt++) {
            LDSM_X4(qh[kt][0], qh[kt][1], qh[kt][2], qh[kt][3], qa + kt * 32);
            LDSM_X4(ql[kt][0], ql[kt][1], ql[kt][2], ql[kt][3], qa + 18432 + kt * 32);
        }
    }

    float acc[8][4];
#pragma unroll
    for (int nt = 0; nt < 8; nt++)
#pragma unroll
        for (int r = 0; r < 4; r++) acc[nt][r] = 0.f;
    float m0 = -1e30f, m1 = -1e30f, l0 = 0.f, l1 = 0.f;

    const int row0 = r0 + w * 16 + (lane >> 2);
    const int row1 = row0 + 8;
    const int ktiles = 2 * it + 2;
    const int diag0 = 2 * it;
    const uint32_t brow = (uint32_t)(((lane >> 4) << 3) + (lane & 7));
    const uint32_t bko  = (uint32_t)(((lane >> 3) & 1) << 4);
    const int rgv = tid >> 4, cgv = tid & 15;

    KVPre pre;
    at_prefetch(khg, klg, vhg, vlg, 0, tid, pre);

    for (int kc = 0; kc < ktiles; kc++) {
        __syncthreads();          // previous tile consumed (or Q frags loaded)

        // ---- store prefetched K (K-major) hi/lo: straight copies ----
#pragma unroll
        for (int i = 0; i < 2; i++) {
            int idx = tid + (i << 8);
            int row = idx >> 3, c16 = idx & 7;
            uint32_t off = (uint32_t)(row * AT_STRB + (c16 << 4));
            *(uint4*)(smc + AT_K_HI + off) = pre.kh[i];
            *(uint4*)(smc + AT_K_LO + off) = pre.kl[i];
        }
        // ---- store prefetched V transposed: PRMT 4x4 bf16 transpose ----
        {
            uint32_t inh[4][2] = {{pre.vh[0].x, pre.vh[0].y}, {pre.vh[1].x, pre.vh[1].y},
                                  {pre.vh[2].x, pre.vh[2].y}, {pre.vh[3].x, pre.vh[3].y}};
            uint32_t inl[4][2] = {{pre.vl[0].x, pre.vl[0].y}, {pre.vl[1].x, pre.vl[1].y},
                                  {pre.vl[2].x, pre.vl[2].y}, {pre.vl[3].x, pre.vl[3].y}};
#pragma unroll
            for (int dd = 0; dd < 4; dd++) {
                int col = (cgv << 2) + dd;
                int q = dd >> 1;
                uint32_t sel = (dd & 1) ? 0x7632u : 0x5410u;
                uint32_t h01, h23, l01, l23;
                PRMT(h01, inh[0][q], inh[1][q], sel);
                PRMT(h23, inh[2][q], inh[3][q], sel);
                PRMT(l01, inl[0][q], inl[1][q], sel);
                PRMT(l23, inl[2][q], inl[3][q], sel);
                uint32_t sw = (uint32_t)(((col >> 3) & 3) << 4);
                uint32_t byte = (uint32_t)(col * AT_STRB) + (((uint32_t)(rgv << 3)) ^ sw);
                *(uint2*)(smc + AT_V_HI + byte) = make_uint2(h01, h23);
                *(uint2*)(smc + AT_V_LO + byte) = make_uint2(l01, l23);
            }
        }
        __syncthreads();

        // prefetch next tile's gmem data (overlaps with MMAs below)
        if (kc + 1 < ktiles) at_prefetch(khg, klg, vhg, vlg, kc + 1, tid, pre);

        // fully-masked tile for this warp? (cols all > max row) -> skip compute.
        // Skipped contributions were exact zeros (exp underflow) and alpha=1.
        if (kc * 64 > r0 + w * 16 + 15) continue;

        // ---- S = Q K^T (split, 3 terms, term-major issue) ----
        float s[8][4];
#pragma unroll
        for (int nt = 0; nt < 8; nt++)
#pragma unroll
            for (int r = 0; r < 4; r++) s[nt][r] = 0.f;
#pragma unroll
        for (int kt = 0; kt < 4; kt++) {
            uint32_t bh[8][2], bl[8][2];
#pragma unroll
            for (int p = 0; p < 4; p++) {
                uint32_t bd = sb + AT_K_HI + (p * 16 + brow) * AT_STRB + kt * 32 + bko;
                LDSM_X4(bh[2*p][0], bh[2*p][1], bh[2*p+1][0], bh[2*p+1][1], bd);
                LDSM_X4(bl[2*p][0], bl[2*p][1], bl[2*p+1][0], bl[2*p+1][1], bd + 9216);
            }
#pragma unroll
            for (int nt = 0; nt < 8; nt++) MMA_BF16(s[nt], qh[kt], bh[nt]);
#pragma unroll
            for (int nt = 0; nt < 8; nt++) MMA_BF16(s[nt], qh[kt], bl[nt]);
#pragma unroll
            for (int nt = 0; nt < 8; nt++) MMA_BF16(s[nt], ql[kt], bh[nt]);
        }
#pragma unroll
        for (int nt = 0; nt < 8; nt++)
#pragma unroll
            for (int r = 0; r < 4; r++) s[nt][r] *= 0.125f;

        // ---- causal mask (diagonal tiles only) ----
        if (kc >= diag0) {
            int colb = kc * 64 + ((lane & 3) << 1);
#pragma unroll
            for (int nt = 0; nt < 8; nt++) {
                int c0 = colb + nt * 8;
                if (c0     > row0) s[nt][0] = -1e30f;
                if (c0 + 1 > row0) s[nt][1] = -1e30f;
                if (c0     > row1) s[nt][2] = -1e30f;
                if (c0 + 1 > row1) s[nt][3] = -1e30f;
            }
        }

        // ---- online softmax (rows r and r+8; 4-lane group reductions) ----
        float mx0 = -1e30f, mx1 = -1e30f;
#pragma unroll
        for (int nt = 0; nt < 8; nt++) {
            mx0 = fmaxf(mx0, fmaxf(s[nt][0], s[nt][1]));
            mx1 = fmaxf(mx1, fmaxf(s[nt][2], s[nt][3]));
        }
        mx0 = fmaxf(mx0, __shfl_xor_sync(0xffffffffu, mx0, 1));
        mx0 = fmaxf(mx0, __shfl_xor_sync(0xffffffffu, mx0, 2));
        mx1 = fmaxf(mx1, __shfl_xor_sync(0xffffffffu, mx1, 1));
        mx1 = fmaxf(mx1, __shfl_xor_sync(0xffffffffu, mx1, 2));
        float nm0 = fmaxf(m0, mx0), nm1 = fmaxf(m1, mx1);
        float sum0 = 0.f, sum1 = 0.f;
#pragma unroll
        for (int nt = 0; nt < 8; nt++) {
            s[nt][0] = __expf(s[nt][0] - nm0); sum0 += s[nt][0];
            s[nt][1] = __expf(s[nt][1] - nm0); sum0 += s[nt][1];
            s[nt][2] = __expf(s[nt][2] - nm1); sum1 += s[nt][2];
            s[nt][3] = __expf(s[nt][3] - nm1); sum1 += s[nt][3];
        }
        sum0 += __shfl_xor_sync(0xffffffffu, sum0, 1);
        sum0 += __shfl_xor_sync(0xffffffffu, sum0, 2);
        sum1 += __shfl_xor_sync(0xffffffffu, sum1, 1);
        sum1 += __shfl_xor_sync(0xffffffffu, sum1, 2);
        float a0 = __expf(m0 - nm0), a1 = __expf(m1 - nm1);
        m0 = nm0; m1 = nm1;
        l0 = l0 * a0 + sum0; l1 = l1 * a1 + sum1;
#pragma unroll
        for (int nt = 0; nt < 8; nt++) {
            acc[nt][0] *= a0; acc[nt][1] *= a0;
            acc[nt][2] *= a1; acc[nt][3] *= a1;
        }

        // ---- repack S accumulator fragments into P A-fragments (hi/lo) ----
        uint32_t ph[4][4], pl[4][4];
#pragma unroll
        for (int kt = 0; kt < 4; kt++) {
            int e = 2 * kt, o = 2 * kt + 1;
            split2(s[e][0], s[e][1], ph[kt][0], pl[kt][0]);
            split2(s[e][2], s[e][3], ph[kt][1], pl[kt][1]);
            split2(s[o][0], s[o][1], ph[kt][2], pl[kt][2]);
            split2(s[o][2], s[o][3], ph[kt][3], pl[kt][3]);
        }

        // ---- O += P @ V (split, 3 terms, term-major issue; swizzled V reads) ----
#pragma unroll
        for (int kt = 0; kt < 4; kt++) {
            uint32_t vh[8][2], vl[8][2];
#pragma unroll
            for (int p = 0; p < 4; p++) {
                uint32_t dlane = (uint32_t)(p * 16) + brow;
                uint32_t sw = ((dlane >> 3) & 3) << 4;
                uint32_t bd = sb + AT_V_HI + dlane * AT_STRB + ((uint32_t)(kt * 32 + bko) ^ sw);
                LDSM_X4(vh[2*p][0], vh[2*p][1], vh[2*p+1][0], vh[2*p+1][1], bd);
                LDSM_X4(vl[2*p][0], vl[2*p][1], vl[2*p+1][0], vl[2*p+1][1], bd + 9216);
            }
#pragma unroll
            for (int nt = 0; nt < 8; nt++) MMA_BF16(acc[nt], ph[kt], vh[nt]);
#pragma unroll
            for (int nt = 0; nt < 8; nt++) MMA_BF16(acc[nt], ph[kt], vl[nt]);
#pragma unroll
            for (int nt = 0; nt < 8; nt++) MMA_BF16(acc[nt], pl[kt], vh[nt]);
        }
    }

    // ---- epilogue: normalize and write bf16 hi/lo (concat head layout) ----
    float inv0 = 1.f / l0, inv1 = 1.f / l1;
    const int tok0 = b * SEQc + row0;
#pragma unroll
    for (int nt = 0; nt < 8; nt++) {
        int col = h * 64 + nt * 8 + ((lane & 3) << 1);
        uint32_t hi, lo;
        split2(acc[nt][0] * inv0, acc[nt][1] * inv0, hi, lo);
        *(uint32_t*)(ohi + (size_t)tok0 * 1024 + col) = hi;
        *(uint32_t*)(olo + (size_t)tok0 * 1024 + col) = lo;
        split2(acc[nt][2] * inv1, acc[nt][3] * inv1, hi, lo);
        *(uint32_t*)(ohi + (size_t)(tok0 + 8) * 1024 + col) = hi;
        *(uint32_t*)(olo + (size_t)(tok0 + 8) * 1024 + col) = lo;
    }
}

// ---------------- LayerNorm + residual ----------------
template<bool SPLITO>
__global__ void ln_residual_kernel(const float* __restrict__ resid,
                                   const float* __restrict__ v,
                                   const float* __restrict__ g,
                                   const float* __restrict__ beta,
                                   float* __restrict__ out,
                                   __nv_bfloat16* __restrict__ ohi,
                                   __nv_bfloat16* __restrict__ olo) {
    __shared__ float red[16];
    const int row = blockIdx.x;
    const int t = threadIdx.x;
    const float* vr = v + (size_t)row * D_MODELc;
    float4 xv = *(const float4*)(vr + t * 4);
    float s  = xv.x + xv.y + xv.z + xv.w;
    float s2 = xv.x * xv.x + xv.y * xv.y + xv.z * xv.z + xv.w * xv.w;
#pragma unroll
    for (int o = 16; o; o >>= 1) {
        s  += __shfl_xor_sync(0xffffffffu, s,  o);
        s2 += __shfl_xor_sync(0xffffffffu, s2, o);
    }
    int wid = t >> 5;
    if ((t & 31) == 0) { red[wid] = s; red[8 + wid] = s2; }
    __syncthreads();
    float S = 0.f, S2 = 0.f;
#pragma unroll
    for (int i = 0; i < 8; i++) { S += red[i]; S2 += red[8 + i]; }
    float mu   = S * (1.f / D_MODELc);
    float var  = S2 * (1.f / D_MODELc) - mu * mu;
    float rstd = rsqrtf(var + LN_EPSc);

    int c = t * 4;
    float4 rr = *(const float4*)(resid + (size_t)row * D_MODELc + c);
    float4 gg = *(const float4*)(g + c);
    float4 bb = *(const float4*)(beta + c);
    float4 o;
    o.x = rr.x + (xv.x - mu) * rstd * gg.x + bb.x;
    o.y = rr.y + (xv.y - mu) * rstd * gg.y + bb.y;
    o.z = rr.z + (xv.z - mu) * rstd * gg.z + bb.z;
    o.w = rr.w + (xv.w - mu) * rstd * gg.w + bb.w;
    *(float4*)(out + (size_t)row * D_MODELc + c) = o;
    if (SPLITO) {
        uint32_t h0, l0, h1, l1;
        split2(o.x, o.y, h0, l0);
        split2(o.z, o.w, h1, l1);
        *(uint2*)(ohi + (size_t)row * D_MODELc + c) = make_uint2(h0, h1);
        *(uint2*)(olo + (size_t)row * D_MODELc + c) = make_uint2(l0, l1);
    }
}

// ---------------- launch ----------------
extern "C" void kernel_launch(void* const* d_in, const int* in_sizes, int n_in,
                              void* d_out, int out_size) {
    (void)in_sizes; (void)n_in; (void)out_size;
    const float* x     = (const float*)d_in[0];
    const float* wq    = (const float*)d_in[1];
    const float* wk    = (const float*)d_in[2];
    const float* wv    = (const float*)d_in[3];
    const float* wo    = (const float*)d_in[4];
    const float* w_in  = (const float*)d_in[5];
    const float* b_in  = (const float*)d_in[6];
    const float* w_out = (const float*)d_in[7];
    const float* b_out = (const float*)d_in[8];
    const float* g1    = (const float*)d_in[9];
    const float* bt1   = (const float*)d_in[10];
    const float* g2    = (const float*)d_in[11];
    const float* bt2   = (const float*)d_in[12];
    float* out = (float*)d_out;

    float *proj, *x1, *mlp;
    __nv_bfloat16 *qkvh, *qkvl, *ahi, *alo, *mh, *ml;
    __nv_bfloat16 *wqh, *wql, *woh, *wol, *wih, *wil, *wgh, *wgl;
    cudaGetSymbolAddress((void**)&proj, g_proj);
    cudaGetSymbolAddress((void**)&x1,   g_x1);
    cudaGetSymbolAddress((void**)&mlp,  g_mlp);
    cudaGetSymbolAddress((void**)&qkvh, g_qkvh);
    cudaGetSymbolAddress((void**)&qkvl, g_qkvl);
    cudaGetSymbolAddress((void**)&ahi,  g_ahi);
    cudaGetSymbolAddress((void**)&alo,  g_alo);
    cudaGetSymbolAddress((void**)&mh,   g_mlph_hi);
    cudaGetSymbolAddress((void**)&ml,   g_mlph_lo);
    cudaGetSymbolAddress((void**)&wqh,  g_wqh);
    cudaGetSymbolAddress((void**)&wql,  g_wql);
    cudaGetSymbolAddress((void**)&woh,  g_woh);
    cudaGetSymbolAddress((void**)&wol,  g_wol);
    cudaGetSymbolAddress((void**)&wih,  g_wih);
    cudaGetSymbolAddress((void**)&wil,  g_wil);
    cudaGetSymbolAddress((void**)&wgh,  g_wgh);
    cudaGetSymbolAddress((void**)&wgl,  g_wgl);

    cudaFuncSetAttribute(tc_gemm_kernel<false, false>, cudaFuncAttributeMaxDynamicSharedMemorySize, TG_SMEM);
    cudaFuncSetAttribute(tc_gemm_kernel<false, true>,  cudaFuncAttributeMaxDynamicSharedMemorySize, TG_SMEM);
    cudaFuncSetAttribute(tc_gemm_kernel<true,  true>,  cudaFuncAttributeMaxDynamicSharedMemorySize, TG_SMEM);
    cudaFuncSetAttribute(attn_mma_kernel, cudaFuncAttributeMaxDynamicSharedMemorySize, AT_SMEM);

    // aux stream + events (created once; host-side objects only, no device memory)
    static cudaStream_t s_aux = [] { cudaStream_t s; cudaStreamCreateWithFlags(&s, cudaStreamNonBlocking); return s; }();
    static cudaEvent_t ev_fork = [] { cudaEvent_t e; cudaEventCreateWithFlags(&e, cudaEventDisableTiming); return e; }();
    static cudaEvent_t ev_w0 = [] { cudaEvent_t e; cudaEventCreateWithFlags(&e, cudaEventDisableTiming); return e; }();
    static cudaEvent_t ev_w1 = [] { cudaEvent_t e; cudaEventCreateWithFlags(&e, cudaEventDisableTiming); return e; }();
    static cudaEvent_t ev_w2 = [] { cudaEvent_t e; cudaEventCreateWithFlags(&e, cudaEventDisableTiming); return e; }();
    static cudaEvent_t ev_w3 = [] { cudaEvent_t e; cudaEventCreateWithFlags(&e, cudaEventDisableTiming); return e; }();

    dim3 tsb(32, 8);

    // ---- fork: weight transposes on aux stream, overlapped with stream-0 compute ----
    cudaEventRecord(ev_fork, 0);
    cudaStreamWaitEvent(s_aux, ev_fork, 0);
    qkv_tsplit_kernel<<<dim3(2, 32, 48), tsb, 0, s_aux>>>(wq, wk, wv, wqh, wql);
    cudaEventRecord(ev_w0, s_aux);
    tsplit_kernel<<<dim3(32, 32), tsb, 0, s_aux>>>(wo, woh, wol, 1024, 1024);
    cudaEventRecord(ev_w1, s_aux);
    tsplit_kernel<<<dim3(128, 32), tsb, 0, s_aux>>>(w_in, wih, wil, 1024, 4096);
    cudaEventRecord(ev_w2, s_aux);
    tsplit_kernel<<<dim3(32, 128), tsb, 0, s_aux>>>(w_out, wgh, wgl, 4096, 1024);
    cudaEventRecord(ev_w3, s_aux);

    // ---- stream 0: main compute chain ----
    asplit_kernel<<<(NTOK * D_MODELc / 4 + 255) / 256, 256>>>(x, ahi, alo, NTOK * D_MODELc / 4);

    cudaStreamWaitEvent(0, ev_w0, 0);
    tc_gemm_kernel<false, true><<<dim3(24, 32), 128, TG_SMEM>>>(
        ahi, alo, wqh, wql, nullptr, nullptr, qkvh, qkvl, NTOK, 3072, 1024);

    attn_mma_kernel<<<dim3(SEQc / 128, BATCHc * 16), 256, AT_SMEM>>>(qkvh, qkvl, ahi, alo);

    cudaStreamWaitEvent(0, ev_w1, 0);
    tc_gemm_kernel<false, false><<<dim3(8, 32), 128, TG_SMEM>>>(
        ahi, alo, woh, wol, nullptr, proj, nullptr, nullptr, NTOK, 1024, 1024);

    ln_residual_kernel<true><<<NTOK, 256>>>(x, proj, g1, bt1, x1, ahi, alo);

    cudaStreamWaitEvent(0, ev_w2, 0);
    tc_gemm_kernel<true, true><<<dim3(32, 32), 128, TG_SMEM>>>(
        ahi, alo, wih, wil, b_in, nullptr, mh, ml, NTOK, 4096, 1024);

    cudaStreamWaitEvent(0, ev_w3, 0);
    tc_gemm_kernel<false, false><<<dim3(8, 32), 128, TG_SMEM>>>(
        mh, ml, wgh, wgl, b_out, mlp, nullptr, nullptr, NTOK, 1024, 4096);

    ln_residual_kernel<false><<<NTOK, 256>>>(x1, mlp, g2, bt2, out, nullptr, nullptr);
}

// round 15
// speedup vs baseline: 1.5858x; 1.1315x over previous
#include <cuda_runtime.h>
#include <cuda_bf16.h>
#include <cstdint>
#include <math.h>

// ---------------- problem constants ----------------
#define D_MODELc 1024
#define SEQc     2048
#define BATCHc   2
#define NTOK     (BATCHc*SEQc)     // 4096 tokens
#define D_MLPc   4096
#define LN_EPSc  1e-5f

// ---------------- device scratch (no runtime allocation allowed) ----------------
__device__ float g_proj[(size_t)NTOK * D_MODELc];               // head_out @ wo
__device__ float g_x1  [(size_t)NTOK * D_MODELc];               // x + LN1(proj)
__device__ float g_mlp [(size_t)NTOK * D_MODELc];               // mlp output
__device__ __nv_bfloat16 g_qkvh[(size_t)NTOK * 3 * D_MODELc];   // qkv split hi
__device__ __nv_bfloat16 g_qkvl[(size_t)NTOK * 3 * D_MODELc];   // qkv split lo
__device__ __nv_bfloat16 g_mlph_hi[(size_t)NTOK * D_MLPc];      // relu(x1@w_in+b_in) split
__device__ __nv_bfloat16 g_mlph_lo[(size_t)NTOK * D_MLPc];
__device__ __nv_bfloat16 g_ahi[(size_t)NTOK * D_MODELc];        // activation split (reused)
__device__ __nv_bfloat16 g_alo[(size_t)NTOK * D_MODELc];
// dedicated weight buffers (enable aux-stream overlap with no reuse hazards)
__device__ __nv_bfloat16 g_wqh[(size_t)3072 * 1024], g_wql[(size_t)3072 * 1024];
__device__ __nv_bfloat16 g_woh[(size_t)1024 * 1024], g_wol[(size_t)1024 * 1024];
__device__ __nv_bfloat16 g_wih[(size_t)4096 * 1024], g_wil[(size_t)4096 * 1024];
__device__ __nv_bfloat16 g_wgh[(size_t)1024 * 4096], g_wgl[(size_t)1024 * 4096];

// ================= PTX helpers (baseline sm_80+ features only) =================
__device__ __forceinline__ uint32_t smem_u32(const void* p) {
    uint32_t a;
    asm("{ .reg .u64 t; cvta.to.shared.u64 t, %1; cvt.u32.u64 %0, t; }" : "=r"(a) : "l"(p));
    return a;
}
#define CP_ASYNC16(dst, src) \
    asm volatile("cp.async.cg.shared.global [%0], [%1], 16;" :: "r"(dst), "l"(src))
#define CP_COMMIT()  asm volatile("cp.async.commit_group;" ::: "memory")
#define CP_WAIT0()   asm volatile("cp.async.wait_group 0;" ::: "memory")
#define CP_WAIT1()   asm volatile("cp.async.wait_group 1;" ::: "memory")
#define LDSM_X4(r0, r1, r2, r3, addr) \
    asm volatile("ldmatrix.sync.aligned.m8n8.x4.shared.b16 {%0,%1,%2,%3}, [%4];" \
        : "=r"(r0), "=r"(r1), "=r"(r2), "=r"(r3) : "r"(addr))
#define MMA_BF16(d, a, b) \
    asm volatile("mma.sync.aligned.m16n8k16.row.col.f32.bf16.bf16.f32 " \
        "{%0,%1,%2,%3},{%4,%5,%6,%7},{%8,%9},{%0,%1,%2,%3};" \
        : "+f"((d)[0]), "+f"((d)[1]), "+f"((d)[2]), "+f"((d)[3]) \
        : "r"((a)[0]), "r"((a)[1]), "r"((a)[2]), "r"((a)[3]), "r"((b)[0]), "r"((b)[1]))
#define PRMT(d, a, b, sel) \
    asm("prmt.b32 %0, %1, %2, %3;" : "=r"(d) : "r"(a), "r"(b), "r"(sel))

// split two fp32 into packed bf16 hi pair + lo (residual) pair
__device__ __forceinline__ void split2(float a, float b, uint32_t& hi, uint32_t& lo) {
    __nv_bfloat16 ha = __float2bfloat16(a), hb = __float2bfloat16(b);
    __nv_bfloat16 la = __float2bfloat16(a - __bfloat162float(ha));
    __nv_bfloat16 lb = __float2bfloat16(b - __bfloat162float(hb));
    __nv_bfloat162 H(ha, hb), L(la, lb);
    hi = *(uint32_t*)&H; lo = *(uint32_t*)&L;
}

// ================= split / transpose kernels =================
__global__ void asplit_kernel(const float* __restrict__ src,
                              __nv_bfloat16* __restrict__ dhi,
                              __nv_bfloat16* __restrict__ dlo, int n4) {
    int i = blockIdx.x * blockDim.x + threadIdx.x;
    if (i >= n4) return;
    float4 v = ((const float4*)src)[i];
    uint32_t h0, l0, h1, l1;
    split2(v.x, v.y, h0, l0);
    split2(v.z, v.w, h1, l1);
    ((uint2*)dhi)[i] = make_uint2(h0, h1);
    ((uint2*)dlo)[i] = make_uint2(l0, l1);
}

// tiled transpose+split: src [R][C] fp32 -> dst [C][R] bf16 hi/lo (vectorized stores)
__global__ void tsplit_kernel(const float* __restrict__ src,
                              __nv_bfloat16* __restrict__ dhi,
                              __nv_bfloat16* __restrict__ dlo, int R, int C) {
    __shared__ float t[32][33];
    int c0 = blockIdx.x * 32, r0 = blockIdx.y * 32;
    int tx = threadIdx.x, ty = threadIdx.y;   // (32, 8)
#pragma unroll
    for (int i = 0; i < 4; i++)
        t[ty + i*8][tx] = src[(size_t)(r0 + ty + i*8) * C + c0 + tx];
    __syncthreads();
    int tid = ty * 32 + tx;
    int sy = tid >> 3;        // 0..31 -> c
    int sx = tid & 7;         // 0..7  -> r group of 4
    float v0 = t[sx*4+0][sy], v1 = t[sx*4+1][sy];
    float v2 = t[sx*4+2][sy], v3 = t[sx*4+3][sy];
    uint32_t h0, l0, h1, l1;
    split2(v0, v1, h0, l0);
    split2(v2, v3, h1, l1);
    size_t o = (size_t)(c0 + sy) * R + r0 + sx * 4;
    *(uint2*)(dhi + o) = make_uint2(h0, h1);
    *(uint2*)(dlo + o) = make_uint2(l0, l1);
}

// wq/wk/wv [16][1024][64] -> Wt [3072][1024] bf16 hi/lo
__global__ void qkv_tsplit_kernel(const float* __restrict__ wq, const float* __restrict__ wk,
                                  const float* __restrict__ wv,
                                  __nv_bfloat16* __restrict__ dhi,
                                  __nv_bfloat16* __restrict__ dlo) {
    __shared__ float t[32][33];
    int z = blockIdx.z, p = z >> 4, h = z & 15;
    const float* src = (p == 0 ? wq : (p == 1 ? wk : wv)) + (size_t)h * 1024 * 64;
    int c0 = blockIdx.x * 32, r0 = blockIdx.y * 32;
    int tx = threadIdx.x, ty = threadIdx.y;
#pragma unroll
    for (int i = 0; i < 4; i++)
        t[ty + i*8][tx] = src[(size_t)(r0 + ty + i*8) * 64 + c0 + tx];
    __syncthreads();
    int nbase = (p << 10) + (h << 6);
    int tid = ty * 32 + tx;
    int sy = tid >> 3;
    int sx = tid & 7;
    float v0 = t[sx*4+0][sy], v1 = t[sx*4+1][sy];
    float v2 = t[sx*4+2][sy], v3 = t[sx*4+3][sy];
    uint32_t h0, l0, h1, l1;
    split2(v0, v1, h0, l0);
    split2(v2, v3, h1, l1);
    size_t o = (size_t)(nbase + c0 + sy) * 1024 + r0 + sx * 4;
    *(uint2*)(dhi + o) = make_uint2(h0, h1);
    *(uint2*)(dlo + o) = make_uint2(l0, l1);
}

// ================= HMMA split-bf16 GEMM (mma.sync m16n8k16) =================
// 128x128 CTA tile, 4 warps (64x64 each), BK=32, 3-stage cp.async, 2 CTAs/SM.
// Row stride 64B, swizzle slot = c16 ^ ((row>>1)&3): over 8 consecutive rows the
// addresses (row&1)*64 + slot*16 cover all eight 16B chunks of the 128B bank
// span exactly once -> conflict-free ldsm AND conflict-free 16B-aligned cp.async.
// Stage 32KB, 3 stages = 96KB/CTA -> 2 CTAs/SM (192KB <= 228KB).
// wait_group(1): each chunk's loads get ~2 chunk-times of latency cover.
// Term-major MMA issue; per-accumulator order unchanged -> bit-identical numerics.
#define TG_MAT   8192       // 128 rows * 64B
#define TG_STAGE 32768
#define TG_SMEM  98304      // 3 stages

__device__ __forceinline__ uint32_t tg_sw(uint32_t row, uint32_t c16) {
    return (row << 6) + ((c16 ^ ((row >> 1) & 3u)) << 4);
}

__device__ __forceinline__ void tg_load(
        const __nv_bfloat16* __restrict__ Ah, const __nv_bfloat16* __restrict__ Al,
        const __nv_bfloat16* __restrict__ Bh, const __nv_bfloat16* __restrict__ Bl,
        int K, int k0, uint32_t sbase, int tid) {
#pragma unroll
    for (int j = 0; j < 4; j++) {
        int idx = tid + (j << 7);      // 128 threads, 512 chunks per matrix
        uint32_t row = (uint32_t)(idx >> 2), c16 = (uint32_t)(idx & 3);
        uint32_t d = sbase + tg_sw(row, c16);
        const size_t go = (size_t)row * K + k0 + (c16 << 3);
        CP_ASYNC16(d,              Ah + go);
        CP_ASYNC16(d +     TG_MAT, Al + go);
        CP_ASYNC16(d + 2 * TG_MAT, Bh + go);
        CP_ASYNC16(d + 3 * TG_MAT, Bl + go);
    }
}

template<bool RELU, bool SPLITO>
__global__ __launch_bounds__(128, 2)
void tc_gemm_kernel(const __nv_bfloat16* __restrict__ Ahi, const __nv_bfloat16* __restrict__ Alo,
                    const __nv_bfloat16* __restrict__ Bhi, const __nv_bfloat16* __restrict__ Blo,
                    const float* __restrict__ bias, float* __restrict__ C,
                    __nv_bfloat16* __restrict__ Chi, __nv_bfloat16* __restrict__ Clo,
                    int M, int N, int K) {
    extern __shared__ char smem[];
    const uint32_t sb = smem_u32(smem);
    const int tid = threadIdx.x, wid = tid >> 5, lane = tid & 31;
    const int wm = wid >> 1, wn = wid & 1;           // warp grid 2(m) x 2(n), 64x64 each
    const int m0 = blockIdx.y * 128, n0 = blockIdx.x * 128;

    const __nv_bfloat16* pAh = Ahi + (size_t)m0 * K;
    const __nv_bfloat16* pAl = Alo + (size_t)m0 * K;
    const __nv_bfloat16* pBh = Bhi + (size_t)n0 * K;
    const __nv_bfloat16* pBl = Blo + (size_t)n0 * K;

    float acc[4][8][4];
#pragma unroll
    for (int i = 0; i < 4; i++)
#pragma unroll
        for (int j = 0; j < 8; j++)
#pragma unroll
            for (int r = 0; r < 4; r++) acc[i][j][r] = 0.f;

    const int nchunk = K >> 5;
    tg_load(pAh, pAl, pBh, pBl, K, 0, sb, tid);
    CP_COMMIT();
    if (nchunk > 1) {
        tg_load(pAh, pAl, pBh, pBl, K, 32, sb + TG_STAGE, tid);
        CP_COMMIT();
    }

    const uint32_t a_row  = (uint32_t)(wm * 64 + (lane & 15));
    const uint32_t a_c16  = (uint32_t)(lane >> 4);          // + ks*2
    const uint32_t b_rowl = (uint32_t)(((lane >> 4) << 3) + (lane & 7));
    const uint32_t b_c16  = (uint32_t)((lane >> 3) & 1);    // + ks*2

    for (int c = 0; c < nchunk; c++) {
        if (c + 1 < nchunk) { CP_WAIT1(); } else { CP_WAIT0(); }
        __syncthreads();
        if (c + 2 < nchunk) {
            tg_load(pAh, pAl, pBh, pBl, K, (c + 2) << 5,
                    sb + (uint32_t)((c + 2) % 3) * TG_STAGE, tid);
            CP_COMMIT();
        }

        const uint32_t st = sb + (uint32_t)(c % 3) * TG_STAGE;
#pragma unroll
        for (int ks = 0; ks < 2; ks++) {
            uint32_t ah[4][4], al[4][4], bh[8][2], bl[8][2];
            const uint32_t ca = (uint32_t)(ks * 2) + a_c16;
            const uint32_t cb = (uint32_t)(ks * 2) + b_c16;
#pragma unroll
            for (int mt = 0; mt < 4; mt++) {
                uint32_t ad = st + tg_sw(a_row + (uint32_t)(mt * 16), ca);
                LDSM_X4(ah[mt][0], ah[mt][1], ah[mt][2], ah[mt][3], ad);
                LDSM_X4(al[mt][0], al[mt][1], al[mt][2], al[mt][3], ad + TG_MAT);
            }
#pragma unroll
            for (int p = 0; p < 4; p++) {
                uint32_t bd = st + 2 * TG_MAT +
                              tg_sw((uint32_t)(wn * 64 + p * 16) + b_rowl, cb);
                LDSM_X4(bh[2*p][0], bh[2*p][1], bh[2*p+1][0], bh[2*p+1][1], bd);
                LDSM_X4(bl[2*p][0], bl[2*p][1], bl[2*p+1][0], bl[2*p+1][1], bd + TG_MAT);
            }
            // term-major: 32 independent MMAs between accumulator reuses
#pragma unroll
            for (int mt = 0; mt < 4; mt++)
#pragma unroll
                for (int nt = 0; nt < 8; nt++) MMA_BF16(acc[mt][nt], ah[mt], bh[nt]);
#pragma unroll
            for (int mt = 0; mt < 4; mt++)
#pragma unroll
                for (int nt = 0; nt < 8; nt++) MMA_BF16(acc[mt][nt], ah[mt], bl[nt]);
#pragma unroll
            for (int mt = 0; mt < 4; mt++)
#pragma unroll
                for (int nt = 0; nt < 8; nt++) MMA_BF16(acc[mt][nt], al[mt], bh[nt]);
        }
    }

#pragma unroll
    for (int mt = 0; mt < 4; mt++) {
        const int r0 = m0 + wm * 64 + mt * 16 + (lane >> 2);
#pragma unroll
        for (int nt = 0; nt < 8; nt++) {
            const int c0 = n0 + wn * 64 + nt * 8 + ((lane & 3) << 1);
            float bx = bias ? bias[c0]     : 0.f;
            float by = bias ? bias[c0 + 1] : 0.f;
            float v0 = acc[mt][nt][0] + bx, v1 = acc[mt][nt][1] + by;
            float v2 = acc[mt][nt][2] + bx, v3 = acc[mt][nt][3] + by;
            if (RELU) {
                v0 = fmaxf(v0, 0.f); v1 = fmaxf(v1, 0.f);
                v2 = fmaxf(v2, 0.f); v3 = fmaxf(v3, 0.f);
            }
            if (SPLITO) {
                uint32_t hi, lo;
                split2(v0, v1, hi, lo);
                *(uint32_t*)(Chi + (size_t)r0 * N + c0) = hi;
                *(uint32_t*)(Clo + (size_t)r0 * N + c0) = lo;
                split2(v2, v3, hi, lo);
                *(uint32_t*)(Chi + (size_t)(r0 + 8) * N + c0) = hi;
                *(uint32_t*)(Clo + (size_t)(r0 + 8) * N + c0) = lo;
            } else {
                *(float2*)(C + (size_t)r0 * N + c0)       = make_float2(v0, v1);
                *(float2*)(C + (size_t)(r0 + 8) * N + c0) = make_float2(v2, v3);
            }
        }
    }
}

// ================= tensor-core flash attention (causal, split-bf16) =================
// R14 kernel: pre-split inputs, term-major issue, fully-masked-tile skip.
#define AT_STRB 144            // smem row stride bytes (72 bf16)
#define AT_K_HI 0
#define AT_K_LO 9216
#define AT_V_HI 18432
#define AT_V_LO 27648
#define AT_SMEM 36864          // Q staging reuses region: hi@0, lo@18432

struct KVPre { uint4 kh[2], kl[2]; uint2 vh[4], vl[4]; };

__device__ __forceinline__ void at_prefetch(
        const __nv_bfloat16* __restrict__ khg, const __nv_bfloat16* __restrict__ klg,
        const __nv_bfloat16* __restrict__ vhg, const __nv_bfloat16* __restrict__ vlg,
        int kc, int tid, KVPre& p) {
    const int rgv = tid >> 4, cgv = tid & 15;
#pragma unroll
    for (int i = 0; i < 2; i++) {
        int idx = tid + (i << 8);
        int row = idx >> 3, c16 = idx & 7;
        size_t o = (size_t)(kc * 64 + row) * 3072 + (c16 << 3);
        p.kh[i] = *(const uint4*)(khg + o);
        p.kl[i] = *(const uint4*)(klg + o);
    }
#pragma unroll
    for (int i = 0; i < 4; i++) {
        size_t o = (size_t)(kc * 64 + 4 * rgv + i) * 3072 + (cgv << 2);
        p.vh[i] = *(const uint2*)(vhg + o);
        p.vl[i] = *(const uint2*)(vlg + o);
    }
}

__global__ __launch_bounds__(256)
void attn_mma_kernel(const __nv_bfloat16* __restrict__ qkvh,
                     const __nv_bfloat16* __restrict__ qkvl,
                     __nv_bfloat16* __restrict__ ohi,
                     __nv_bfloat16* __restrict__ olo) {
    extern __shared__ char smc[];
    const uint32_t sb = smem_u32(smc);
    const int b = blockIdx.y >> 4, h = blockIdx.y & 15;
    const int it = (int)gridDim.x - 1 - (int)blockIdx.x;    // heavy tiles first
    const int r0 = it * 128;
    const int tid = threadIdx.x, w = tid >> 5, lane = tid & 31;

    const size_t base = (size_t)b * SEQc * 3072 + (size_t)(h * 64);
    const __nv_bfloat16* qhg = qkvh + base;
    const __nv_bfloat16* qlg = qkvl + base;
    const __nv_bfloat16* khg = qkvh + base + 1024;
    const __nv_bfloat16* klg = qkvl + base + 1024;
    const __nv_bfloat16* vhg = qkvh + base + 2048;
    const __nv_bfloat16* vlg = qkvl + base + 2048;

    // ---- stage Q (128x64 bf16 hi/lo) into smem: pure copies ----
#pragma unroll
    for (int i = 0; i < 4; i++) {
        int idx = tid + (i << 8);          // 0..1023
        int row = idx >> 3, c16 = idx & 7;
        size_t o = (size_t)(r0 + row) * 3072 + (c16 << 3);
        uint32_t off = (uint32_t)(row * AT_STRB + (c16 << 4));
        *(uint4*)(smc + off)         = *(const uint4*)(qhg + o);
        *(uint4*)(smc + 18432 + off) = *(const uint4*)(qlg + o);
    }
    __syncthreads();

    // Q fragments (register-resident for the whole row tile)
    uint32_t qh[4][4], ql[4][4];
    {
        uint32_t qa = sb + (uint32_t)((w * 16 + (lane & 15)) * AT_STRB) + (uint32_t)(((lane >> 4) << 4));
#pragma unroll
        for (int kt = 0; kt < 4; kt++) {
            LDSM_X4(qh[kt][0], qh[kt][1], qh[kt][2], qh[kt][3], qa + kt * 32);
            LDSM_X4(ql[kt][0], ql[kt][1], ql[kt][2], ql[kt][3], qa + 18432 + kt * 32);
        }
    }

    float acc[8][4];
#pragma unroll
    for (int nt = 0; nt < 8; nt++)
#pragma unroll
        for (int r = 0; r < 4; r++) acc[nt][r] = 0.f;
    float m0 = -1e30f, m1 = -1e30f, l0 = 0.f, l1 = 0.f;

    const int row0 = r0 + w * 16 + (lane >> 2);
    const int row1 = row0 + 8;
    const int ktiles = 2 * it + 2;
    const int diag0 = 2 * it;
    const uint32_t brow = (uint32_t)(((lane >> 4) << 3) + (lane & 7));
    const uint32_t bko  = (uint32_t)(((lane >> 3) & 1) << 4);
    const int rgv = tid >> 4, cgv = tid & 15;

    KVPre pre;
    at_prefetch(khg, klg, vhg, vlg, 0, tid, pre);

    for (int kc = 0; kc < ktiles; kc++) {
        __syncthreads();          // previous tile consumed (or Q frags loaded)

        // ---- store prefetched K (K-major) hi/lo: straight copies ----
#pragma unroll
        for (int i = 0; i < 2; i++) {
            int idx = tid + (i << 8);
            int row = idx >> 3, c16 = idx & 7;
            uint32_t off = (uint32_t)(row * AT_STRB + (c16 << 4));
            *(uint4*)(smc + AT_K_HI + off) = pre.kh[i];
            *(uint4*)(smc + AT_K_LO + off) = pre.kl[i];
        }
        // ---- store prefetched V transposed: PRMT 4x4 bf16 transpose ----
        {
            uint32_t inh[4][2] = {{pre.vh[0].x, pre.vh[0].y}, {pre.vh[1].x, pre.vh[1].y},
                                  {pre.vh[2].x, pre.vh[2].y}, {pre.vh[3].x, pre.vh[3].y}};
            uint32_t inl[4][2] = {{pre.vl[0].x, pre.vl[0].y}, {pre.vl[1].x, pre.vl[1].y},
                                  {pre.vl[2].x, pre.vl[2].y}, {pre.vl[3].x, pre.vl[3].y}};
#pragma unroll
            for (int dd = 0; dd < 4; dd++) {
                int col = (cgv << 2) + dd;
                int q = dd >> 1;
                uint32_t sel = (dd & 1) ? 0x7632u : 0x5410u;
                uint32_t h01, h23, l01, l23;
                PRMT(h01, inh[0][q], inh[1][q], sel);
                PRMT(h23, inh[2][q], inh[3][q], sel);
                PRMT(l01, inl[0][q], inl[1][q], sel);
                PRMT(l23, inl[2][q], inl[3][q], sel);
                uint32_t sw = (uint32_t)(((col >> 3) & 3) << 4);
                uint32_t byte = (uint32_t)(col * AT_STRB) + (((uint32_t)(rgv << 3)) ^ sw);
                *(uint2*)(smc + AT_V_HI + byte) = make_uint2(h01, h23);
                *(uint2*)(smc + AT_V_LO + byte) = make_uint2(l01, l23);
            }
        }
        __syncthreads();

        // prefetch next tile's gmem data (overlaps with MMAs below)
        if (kc + 1 < ktiles) at_prefetch(khg, klg, vhg, vlg, kc + 1, tid, pre);

        // fully-masked tile for this warp? (cols all > max row) -> skip compute.
        // Skipped contributions were exact zeros (exp underflow) and alpha=1.
        if (kc * 64 > r0 + w * 16 + 15) continue;

        // ---- S = Q K^T (split, 3 terms, term-major issue) ----
        float s[8][4];
#pragma unroll
        for (int nt = 0; nt < 8; nt++)
#pragma unroll
            for (int r = 0; r < 4; r++) s[nt][r] = 0.f;
#pragma unroll
        for (int kt = 0; kt < 4; kt++) {
            uint32_t bh[8][2], bl[8][2];
#pragma unroll
            for (int p = 0; p < 4; p++) {
                uint32_t bd = sb + AT_K_HI + (p * 16 + brow) * AT_STRB + kt * 32 + bko;
                LDSM_X4(bh[2*p][0], bh[2*p][1], bh[2*p+1][0], bh[2*p+1][1], bd);
                LDSM_X4(bl[2*p][0], bl[2*p][1], bl[2*p+1][0], bl[2*p+1][1], bd + 9216);
            }
#pragma unroll
            for (int nt = 0; nt < 8; nt++) MMA_BF16(s[nt], qh[kt], bh[nt]);
#pragma unroll
            for (int nt = 0; nt < 8; nt++) MMA_BF16(s[nt], qh[kt], bl[nt]);
#pragma unroll
            for (int nt = 0; nt < 8; nt++) MMA_BF16(s[nt], ql[kt], bh[nt]);
        }
#pragma unroll
        for (int nt = 0; nt < 8; nt++)
#pragma unroll
            for (int r = 0; r < 4; r++) s[nt][r] *= 0.125f;

        // ---- causal mask (diagonal tiles only) ----
        if (kc >= diag0) {
            int colb = kc * 64 + ((lane & 3) << 1);
#pragma unroll
            for (int nt = 0; nt < 8; nt++) {
                int c0 = colb + nt * 8;
                if (c0     > row0) s[nt][0] = -1e30f;
                if (c0 + 1 > row0) s[nt][1] = -1e30f;
                if (c0     > row1) s[nt][2] = -1e30f;
                if (c0 + 1 > row1) s[nt][3] = -1e30f;
            }
        }

        // ---- online softmax (rows r and r+8; 4-lane group reductions) ----
        float mx0 = -1e30f, mx1 = -1e30f;
#pragma unroll
        for (int nt = 0; nt < 8; nt++) {
            mx0 = fmaxf(mx0, fmaxf(s[nt][0], s[nt][1]));
            mx1 = fmaxf(mx1, fmaxf(s[nt][2], s[nt][3]));
        }
        mx0 = fmaxf(mx0, __shfl_xor_sync(0xffffffffu, mx0, 1));
        mx0 = fmaxf(mx0, __shfl_xor_sync(0xffffffffu, mx0, 2));
        mx1 = fmaxf(mx1, __shfl_xor_sync(0xffffffffu, mx1, 1));
        mx1 = fmaxf(mx1, __shfl_xor_sync(0xffffffffu, mx1, 2));
        float nm0 = fmaxf(m0, mx0), nm1 = fmaxf(m1, mx1);
        float sum0 = 0.f, sum1 = 0.f;
#pragma unroll
        for (int nt = 0; nt < 8; nt++) {
            s[nt][0] = __expf(s[nt][0] - nm0); sum0 += s[nt][0];
            s[nt][1] = __expf(s[nt][1] - nm0); sum0 += s[nt][1];
            s[nt][2] = __expf(s[nt][2] - nm1); sum1 += s[nt][2];
            s[nt][3] = __expf(s[nt][3] - nm1); sum1 += s[nt][3];
        }
        sum0 += __shfl_xor_sync(0xffffffffu, sum0, 1);
        sum0 += __shfl_xor_sync(0xffffffffu, sum0, 2);
        sum1 += __shfl_xor_sync(0xffffffffu, sum1, 1);
        sum1 += __shfl_xor_sync(0xffffffffu, sum1, 2);
        float a0 = __expf(m0 - nm0), a1 = __expf(m1 - nm1);
        m0 = nm0; m1 = nm1;
        l0 = l0 * a0 + sum0; l1 = l1 * a1 + sum1;
#pragma unroll
        for (int nt = 0; nt < 8; nt++) {
            acc[nt][0] *= a0; acc[nt][1] *= a0;
            acc[nt][2] *= a1; acc[nt][3] *= a1;
        }

        // ---- repack S accumulator fragments into P A-fragments (hi/lo) ----
        uint32_t ph[4][4], pl[4][4];
#pragma unroll
        for (int kt = 0; kt < 4; kt++) {
            int e = 2 * kt, o = 2 * kt + 1;
            split2(s[e][0], s[e][1], ph[kt][0], pl[kt][0]);
            split2(s[e][2], s[e][3], ph[kt][1], pl[kt][1]);
            split2(s[o][0], s[o][1], ph[kt][2], pl[kt][2]);
            split2(s[o][2], s[o][3], ph[kt][3], pl[kt][3]);
        }

        // ---- O += P @ V (split, 3 terms, term-major issue; swizzled V reads) ----
#pragma unroll
        for (int kt = 0; kt < 4; kt++) {
            uint32_t vh[8][2], vl[8][2];
#pragma unroll
            for (int p = 0; p < 4; p++) {
                uint32_t dlane = (uint32_t)(p * 16) + brow;
                uint32_t sw = ((dlane >> 3) & 3) << 4;
                uint32_t bd = sb + AT_V_HI + dlane * AT_STRB + ((uint32_t)(kt * 32 + bko) ^ sw);
                LDSM_X4(vh[2*p][0], vh[2*p][1], vh[2*p+1][0], vh[2*p+1][1], bd);
                LDSM_X4(vl[2*p][0], vl[2*p][1], vl[2*p+1][0], vl[2*p+1][1], bd + 9216);
            }
#pragma unroll
            for (int nt = 0; nt < 8; nt++) MMA_BF16(acc[nt], ph[kt], vh[nt]);
#pragma unroll
            for (int nt = 0; nt < 8; nt++) MMA_BF16(acc[nt], ph[kt], vl[nt]);
#pragma unroll
            for (int nt = 0; nt < 8; nt++) MMA_BF16(acc[nt], pl[kt], vh[nt]);
        }
    }

    // ---- epilogue: normalize and write bf16 hi/lo (concat head layout) ----
    float inv0 = 1.f / l0, inv1 = 1.f / l1;
    const int tok0 = b * SEQc + row0;
#pragma unroll
    for (int nt = 0; nt < 8; nt++) {
        int col = h * 64 + nt * 8 + ((lane & 3) << 1);
        uint32_t hi, lo;
        split2(acc[nt][0] * inv0, acc[nt][1] * inv0, hi, lo);
        *(uint32_t*)(ohi + (size_t)tok0 * 1024 + col) = hi;
        *(uint32_t*)(olo + (size_t)tok0 * 1024 + col) = lo;
        split2(acc[nt][2] * inv1, acc[nt][3] * inv1, hi, lo);
        *(uint32_t*)(ohi + (size_t)(tok0 + 8) * 1024 + col) = hi;
        *(uint32_t*)(olo + (size_t)(tok0 + 8) * 1024 + col) = lo;
    }
}

// ---------------- LayerNorm + residual ----------------
template<bool SPLITO>
__global__ void ln_residual_kernel(const float* __restrict__ resid,
                                   const float* __restrict__ v,
                                   const float* __restrict__ g,
                                   const float* __restrict__ beta,
                                   float* __restrict__ out,
                                   __nv_bfloat16* __restrict__ ohi,
                                   __nv_bfloat16* __restrict__ olo) {
    __shared__ float red[16];
    const int row = blockIdx.x;
    const int t = threadIdx.x;
    const float* vr = v + (size_t)row * D_MODELc;
    float4 xv = *(const float4*)(vr + t * 4);
    float s  = xv.x + xv.y + xv.z + xv.w;
    float s2 = xv.x * xv.x + xv.y * xv.y + xv.z * xv.z + xv.w * xv.w;
#pragma unroll
    for (int o = 16; o; o >>= 1) {
        s  += __shfl_xor_sync(0xffffffffu, s,  o);
        s2 += __shfl_xor_sync(0xffffffffu, s2, o);
    }
    int wid = t >> 5;
    if ((t & 31) == 0) { red[wid] = s; red[8 + wid] = s2; }
    __syncthreads();
    float S = 0.f, S2 = 0.f;
#pragma unroll
    for (int i = 0; i < 8; i++) { S += red[i]; S2 += red[8 + i]; }
    float mu   = S * (1.f / D_MODELc);
    float var  = S2 * (1.f / D_MODELc) - mu * mu;
    float rstd = rsqrtf(var + LN_EPSc);

    int c = t * 4;
    float4 rr = *(const float4*)(resid + (size_t)row * D_MODELc + c);
    float4 gg = *(const float4*)(g + c);
    float4 bb = *(const float4*)(beta + c);
    float4 o;
    o.x = rr.x + (xv.x - mu) * rstd * gg.x + bb.x;
    o.y = rr.y + (xv.y - mu) * rstd * gg.y + bb.y;
    o.z = rr.z + (xv.z - mu) * rstd * gg.z + bb.z;
    o.w = rr.w + (xv.w - mu) * rstd * gg.w + bb.w;
    *(float4*)(out + (size_t)row * D_MODELc + c) = o;
    if (SPLITO) {
        uint32_t h0, l0, h1, l1;
        split2(o.x, o.y, h0, l0);
        split2(o.z, o.w, h1, l1);
        *(uint2*)(ohi + (size_t)row * D_MODELc + c) = make_uint2(h0, h1);
        *(uint2*)(olo + (size_t)row * D_MODELc + c) = make_uint2(l0, l1);
    }
}

// ---------------- launch ----------------
extern "C" void kernel_launch(void* const* d_in, const int* in_sizes, int n_in,
                              void* d_out, int out_size) {
    (void)in_sizes; (void)n_in; (void)out_size;
    const float* x     = (const float*)d_in[0];
    const float* wq    = (const float*)d_in[1];
    const float* wk    = (const float*)d_in[2];
    const float* wv    = (const float*)d_in[3];
    const float* wo    = (const float*)d_in[4];
    const float* w_in  = (const float*)d_in[5];
    const float* b_in  = (const float*)d_in[6];
    const float* w_out = (const float*)d_in[7];
    const float* b_out = (const float*)d_in[8];
    const float* g1    = (const float*)d_in[9];
    const float* bt1   = (const float*)d_in[10];
    const float* g2    = (const float*)d_in[11];
    const float* bt2   = (const float*)d_in[12];
    float* out = (float*)d_out;

    float *proj, *x1, *mlp;
    __nv_bfloat16 *qkvh, *qkvl, *ahi, *alo, *mh, *ml;
    __nv_bfloat16 *wqh, *wql, *woh, *wol, *wih, *wil, *wgh, *wgl;
    cudaGetSymbolAddress((void**)&proj, g_proj);
    cudaGetSymbolAddress((void**)&x1,   g_x1);
    cudaGetSymbolAddress((void**)&mlp,  g_mlp);
    cudaGetSymbolAddress((void**)&qkvh, g_qkvh);
    cudaGetSymbolAddress((void**)&qkvl, g_qkvl);
    cudaGetSymbolAddress((void**)&ahi,  g_ahi);
    cudaGetSymbolAddress((void**)&alo,  g_alo);
    cudaGetSymbolAddress((void**)&mh,   g_mlph_hi);
    cudaGetSymbolAddress((void**)&ml,   g_mlph_lo);
    cudaGetSymbolAddress((void**)&wqh,  g_wqh);
    cudaGetSymbolAddress((void**)&wql,  g_wql);
    cudaGetSymbolAddress((void**)&woh,  g_woh);
    cudaGetSymbolAddress((void**)&wol,  g_wol);
    cudaGetSymbolAddress((void**)&wih,  g_wih);
    cudaGetSymbolAddress((void**)&wil,  g_wil);
    cudaGetSymbolAddress((void**)&wgh,  g_wgh);
    cudaGetSymbolAddress((void**)&wgl,  g_wgl);

    cudaFuncSetAttribute(tc_gemm_kernel<false, false>, cudaFuncAttributeMaxDynamicSharedMemorySize, TG_SMEM);
    cudaFuncSetAttribute(tc_gemm_kernel<false, true>,  cudaFuncAttributeMaxDynamicSharedMemorySize, TG_SMEM);
    cudaFuncSetAttribute(tc_gemm_kernel<true,  true>,  cudaFuncAttributeMaxDynamicSharedMemorySize, TG_SMEM);
    cudaFuncSetAttribute(attn_mma_kernel, cudaFuncAttributeMaxDynamicSharedMemorySize, AT_SMEM);

    // aux stream + events (created once; host-side objects only, no device memory)
    static cudaStream_t s_aux = [] { cudaStream_t s; cudaStreamCreateWithFlags(&s, cudaStreamNonBlocking); return s; }();
    static cudaEvent_t ev_fork = [] { cudaEvent_t e; cudaEventCreateWithFlags(&e, cudaEventDisableTiming); return e; }();
    static cudaEvent_t ev_w0 = [] { cudaEvent_t e; cudaEventCreateWithFlags(&e, cudaEventDisableTiming); return e; }();
    static cudaEvent_t ev_w1 = [] { cudaEvent_t e; cudaEventCreateWithFlags(&e, cudaEventDisableTiming); return e; }();
    static cudaEvent_t ev_w2 = [] { cudaEvent_t e; cudaEventCreateWithFlags(&e, cudaEventDisableTiming); return e; }();
    static cudaEvent_t ev_w3 = [] { cudaEvent_t e; cudaEventCreateWithFlags(&e, cudaEventDisableTiming); return e; }();

    dim3 tsb(32, 8);

    // ---- fork: weight transposes on aux stream, overlapped with stream-0 compute ----
    cudaEventRecord(ev_fork, 0);
    cudaStreamWaitEvent(s_aux, ev_fork, 0);
    qkv_tsplit_kernel<<<dim3(2, 32, 48), tsb, 0, s_aux>>>(wq, wk, wv, wqh, wql);
    cudaEventRecord(ev_w0, s_aux);
    tsplit_kernel<<<dim3(32, 32), tsb, 0, s_aux>>>(wo, woh, wol, 1024, 1024);
    cudaEventRecord(ev_w1, s_aux);
    tsplit_kernel<<<dim3(128, 32), tsb, 0, s_aux>>>(w_in, wih, wil, 1024, 4096);
    cudaEventRecord(ev_w2, s_aux);
    tsplit_kernel<<<dim3(32, 128), tsb, 0, s_aux>>>(w_out, wgh, wgl, 4096, 1024);
    cudaEventRecord(ev_w3, s_aux);

    // ---- stream 0: main compute chain ----
    asplit_kernel<<<(NTOK * D_MODELc / 4 + 255) / 256, 256>>>(x, ahi, alo, NTOK * D_MODELc / 4);

    cudaStreamWaitEvent(0, ev_w0, 0);
    tc_gemm_kernel<false, true><<<dim3(24, 32), 128, TG_SMEM>>>(
        ahi, alo, wqh, wql, nullptr, nullptr, qkvh, qkvl, NTOK, 3072, 1024);

    attn_mma_kernel<<<dim3(SEQc / 128, BATCHc * 16), 256, AT_SMEM>>>(qkvh, qkvl, ahi, alo);

    cudaStreamWaitEvent(0, ev_w1, 0);
    tc_gemm_kernel<false, false><<<dim3(8, 32), 128, TG_SMEM>>>(
        ahi, alo, woh, wol, nullptr, proj, nullptr, nullptr, NTOK, 1024, 1024);

    ln_residual_kernel<true><<<NTOK, 256>>>(x, proj, g1, bt1, x1, ahi, alo);

    cudaStreamWaitEvent(0, ev_w2, 0);
    tc_gemm_kernel<true, true><<<dim3(32, 32), 128, TG_SMEM>>>(
        ahi, alo, wih, wil, b_in, nullptr, mh, ml, NTOK, 4096, 1024);

    cudaStreamWaitEvent(0, ev_w3, 0);
    tc_gemm_kernel<false, false><<<dim3(8, 32), 128, TG_SMEM>>>(
        mh, ml, wgh, wgl, b_out, mlp, nullptr, nullptr, NTOK, 1024, 4096);

    ln_residual_kernel<false><<<NTOK, 256>>>(x1, mlp, g2, bt2, out, nullptr, nullptr);
}